// round 1
// baseline (speedup 1.0000x reference)
#include <cuda_runtime.h>
#include <cuda_bf16.h>

#define BB 4
#define SS 2048
#define DD 1024
#define HH 16
#define HDD 64
#define MM (BB*SS)   // 8192

// Scratch (allocation-free rule: __device__ globals)
__device__ float g_q[(size_t)BB*HH*SS*HDD];   // [bh][s][e] 32MB
__device__ float g_k[(size_t)BB*HH*SS*HDD];
__device__ float g_v[(size_t)BB*HH*SS*HDD];
__device__ float g_c[(size_t)MM*DD];          // attn out, concat layout [b,s,D]

#define LD4(dst, ptr) { float4 _t = *(const float4*)(ptr); \
    (dst)[0]=_t.x; (dst)[1]=_t.y; (dst)[2]=_t.z; (dst)[3]=_t.w; }

// ---------------------------------------------------------------------------
// Kernel 1: QKV projection. C[row, (which,h,e)] = sum_d x[row,d]*W[h,d,e]
// BM=128, BN=64 (= one head of one tensor), BK=16, 256 thr, 8x4 microtile.
// ---------------------------------------------------------------------------
__global__ __launch_bounds__(256) void qkv_kernel(
    const float* __restrict__ x, const float* __restrict__ Wq,
    const float* __restrict__ Wk, const float* __restrict__ Wv)
{
    __shared__ float As[16][132];   // [k][m], pad 132 (bank rot 4)
    __shared__ float Bs[16][68];    // [k][n], pad 68

    const int rt = blockIdx.x;          // row tile (128 rows)
    const int ct = blockIdx.y;          // 0..47: which*16 + h
    const int which = ct >> 4, h = ct & 15;
    const float* W = (which == 0 ? Wq : which == 1 ? Wk : Wv) + (size_t)h*DD*HDD;
    float* outbuf  = (which == 0 ? g_q : which == 1 ? g_k : g_v);

    const int tid = threadIdx.x;
    const int ry = tid >> 4;            // 0..15 -> rows ry*8..ry*8+7
    const int cx = tid & 15;            // cols cx*4..cx*4+3
    const int m0 = rt * 128;
    const int lr = tid >> 2, sg = tid & 3;

    float acc[8][4];
#pragma unroll
    for (int i = 0; i < 8; i++)
#pragma unroll
        for (int j = 0; j < 4; j++) acc[i][j] = 0.f;

    for (int k0 = 0; k0 < DD; k0 += 16) {
        // A tile: 128x16, stored transposed As[k][m]
#pragma unroll
        for (int hf = 0; hf < 2; hf++) {
            int row = lr + hf*64;
            float4 av = *(const float4*)&x[(size_t)(m0+row)*DD + k0 + sg*4];
            As[sg*4+0][row] = av.x; As[sg*4+1][row] = av.y;
            As[sg*4+2][row] = av.z; As[sg*4+3][row] = av.w;
        }
        // B tile: 16x64, direct
        {
            int kk = tid >> 4, s2 = tid & 15;
            float4 bv = *(const float4*)&W[(size_t)(k0+kk)*HDD + s2*4];
            *(float4*)&Bs[kk][s2*4] = bv;
        }
        __syncthreads();
#pragma unroll
        for (int kk = 0; kk < 16; kk++) {
            float a[8], b[4];
            LD4(a,   &As[kk][ry*8]);
            LD4(a+4, &As[kk][ry*8+4]);
            LD4(b,   &Bs[kk][cx*4]);
#pragma unroll
            for (int i = 0; i < 8; i++)
#pragma unroll
                for (int j = 0; j < 4; j++) acc[i][j] += a[i]*b[j];
        }
        __syncthreads();
    }
    // Epilogue: out[((b*H+h)*S+s)*HD + e]
#pragma unroll
    for (int i = 0; i < 8; i++) {
        int r = m0 + ry*8 + i;
        int b = r >> 11, s = r & (SS-1);
        float4 v4 = make_float4(acc[i][0], acc[i][1], acc[i][2], acc[i][3]);
        *(float4*)&outbuf[((size_t)(b*HH + h)*SS + s)*HDD + cx*4] = v4;
    }
}

// ---------------------------------------------------------------------------
// Kernel 2: flash-style causal attention. CTA = (qtile of 64 rows, bh).
// 256 threads; score/PV microtile 4x4 per thread. K stored transposed.
// ---------------------------------------------------------------------------
__global__ __launch_bounds__(256) void attn_kernel() {
    extern __shared__ float sm[];
    float* Qs  = sm;                 // [64][68]  (q rows, d cols), pre-scaled
    float* Kts = Qs  + 64*68;        // [64][68]  (d rows, k cols) TRANSPOSED
    float* Vs  = Kts + 64*68;        // [64][68]  (k rows, d cols)
    float* Ps  = Vs  + 64*68;        // [64][68]  (q rows, k cols)

    const int qt = blockIdx.x;       // 0..31
    const int bh = blockIdx.y;       // 0..63
    const int b = bh >> 4, h = bh & 15;
    const float* qb = g_q + (size_t)bh*SS*HDD;
    const float* kb = g_k + (size_t)bh*SS*HDD;
    const float* vb = g_v + (size_t)bh*SS*HDD;

    const int tid = threadIdx.x;
    const int ry = tid >> 4, cx = tid & 15;

    // Load Q tile, pre-scaled by 1/sqrt(HD)=0.125
    for (int t = tid; t < 64*16; t += 256) {
        int row = t >> 4, sc = t & 15;
        float4 qv = *(const float4*)&qb[(size_t)(qt*64+row)*HDD + sc*4];
        qv.x *= 0.125f; qv.y *= 0.125f; qv.z *= 0.125f; qv.w *= 0.125f;
        *(float4*)&Qs[row*68 + sc*4] = qv;
    }

    float m[4], l[4], o[4][4];
#pragma unroll
    for (int i = 0; i < 4; i++) {
        m[i] = -1e30f; l[i] = 0.f;
#pragma unroll
        for (int j = 0; j < 4; j++) o[i][j] = 0.f;
    }

    for (int kt = 0; kt <= qt; kt++) {
        __syncthreads();  // prior reads of Kts/Vs/Ps done; also fences Q stores (1st iter)
        for (int t = tid; t < 64*16; t += 256) {
            int row = t >> 4, sc = t & 15;  // row = k index
            float4 kv = *(const float4*)&kb[(size_t)(kt*64+row)*HDD + sc*4];
            Kts[(sc*4+0)*68 + row] = kv.x;
            Kts[(sc*4+1)*68 + row] = kv.y;
            Kts[(sc*4+2)*68 + row] = kv.z;
            Kts[(sc*4+3)*68 + row] = kv.w;
            float4 vv = *(const float4*)&vb[(size_t)(kt*64+row)*HDD + sc*4];
            *(float4*)&Vs[row*68 + sc*4] = vv;
        }
        __syncthreads();

        // Scores: s[i][j] = sum_d Q[r_i][d] * K[c_j][d]
        float s[4][4];
#pragma unroll
        for (int i = 0; i < 4; i++)
#pragma unroll
            for (int j = 0; j < 4; j++) s[i][j] = 0.f;

#pragma unroll 8
        for (int d = 0; d < 64; d += 4) {
            float a[4][4], bq[4][4];
#pragma unroll
            for (int i = 0; i < 4; i++) LD4(a[i],  &Qs[(ry*4+i)*68 + d]);
#pragma unroll
            for (int u = 0; u < 4; u++) LD4(bq[u], &Kts[(d+u)*68 + cx*4]);
#pragma unroll
            for (int i = 0; i < 4; i++)
#pragma unroll
                for (int u = 0; u < 4; u++)
#pragma unroll
                    for (int j = 0; j < 4; j++)
                        s[i][j] += a[i][u] * bq[u][j];
        }

        // Causal mask on diagonal tile
        if (kt == qt) {
#pragma unroll
            for (int i = 0; i < 4; i++)
#pragma unroll
                for (int j = 0; j < 4; j++)
                    if (cx*4+j > ry*4+i) s[i][j] = -1e30f;
        }

        // Online softmax. Row group = 16 lanes (same ry), shuffle reduce.
#pragma unroll
        for (int i = 0; i < 4; i++) {
            float rm = fmaxf(fmaxf(s[i][0], s[i][1]), fmaxf(s[i][2], s[i][3]));
#pragma unroll
            for (int off = 8; off >= 1; off >>= 1)
                rm = fmaxf(rm, __shfl_xor_sync(0xffffffffu, rm, off));
            float mnew = fmaxf(m[i], rm);
            float corr = __expf(m[i] - mnew);
            float rs = 0.f;
#pragma unroll
            for (int j = 0; j < 4; j++) { s[i][j] = __expf(s[i][j] - mnew); rs += s[i][j]; }
#pragma unroll
            for (int off = 8; off >= 1; off >>= 1)
                rs += __shfl_xor_sync(0xffffffffu, rs, off);
            l[i] = l[i]*corr + rs;
            m[i] = mnew;
#pragma unroll
            for (int j = 0; j < 4; j++) o[i][j] *= corr;
            *(float4*)&Ps[(ry*4+i)*68 + cx*4] =
                make_float4(s[i][0], s[i][1], s[i][2], s[i][3]);
        }
        __syncthreads();

        // O += P @ V
#pragma unroll 8
        for (int kk = 0; kk < 64; kk += 4) {
            float p[4][4], vv[4][4];
#pragma unroll
            for (int i = 0; i < 4; i++) LD4(p[i],  &Ps[(ry*4+i)*68 + kk]);
#pragma unroll
            for (int u = 0; u < 4; u++) LD4(vv[u], &Vs[(kk+u)*68 + cx*4]);
#pragma unroll
            for (int i = 0; i < 4; i++)
#pragma unroll
                for (int u = 0; u < 4; u++)
#pragma unroll
                    for (int j = 0; j < 4; j++)
                        o[i][j] += p[i][u] * vv[u][j];
        }
    }

    // Epilogue into concat layout [b, s, h*64 + e]
#pragma unroll
    for (int i = 0; i < 4; i++) {
        float inv = 1.0f / l[i];
        size_t grow = (size_t)(b*SS + qt*64 + ry*4 + i);
        *(float4*)&g_c[grow*DD + h*64 + cx*4] =
            make_float4(o[i][0]*inv, o[i][1]*inv, o[i][2]*inv, o[i][3]*inv);
    }
}

// ---------------------------------------------------------------------------
// Kernel 3: output projection y = C @ W_O^T. Same tiling as qkv_kernel;
// B operand transposed from W_O (Bs[k][n] = W_O[n][k]).
// ---------------------------------------------------------------------------
__global__ __launch_bounds__(256) void oproj_kernel(
    const float* __restrict__ Wo, float* __restrict__ y)
{
    __shared__ float As[16][132];
    __shared__ float Bs[16][68];

    const int rt = blockIdx.x, ctn = blockIdx.y;
    const int m0 = rt * 128, n0 = ctn * 64;
    const int tid = threadIdx.x;
    const int ry = tid >> 4, cx = tid & 15;
    const int lr = tid >> 2, sg = tid & 3;

    float acc[8][4];
#pragma unroll
    for (int i = 0; i < 8; i++)
#pragma unroll
        for (int j = 0; j < 4; j++) acc[i][j] = 0.f;

    for (int k0 = 0; k0 < DD; k0 += 16) {
#pragma unroll
        for (int hf = 0; hf < 2; hf++) {
            int row = lr + hf*64;
            float4 av = *(const float4*)&g_c[(size_t)(m0+row)*DD + k0 + sg*4];
            As[sg*4+0][row] = av.x; As[sg*4+1][row] = av.y;
            As[sg*4+2][row] = av.z; As[sg*4+3][row] = av.w;
        }
        {
            int c = tid >> 2, s2 = tid & 3;   // c = output col, s2*4.. = k seg
            float4 wv = *(const float4*)&Wo[(size_t)(n0+c)*DD + k0 + s2*4];
            Bs[s2*4+0][c] = wv.x; Bs[s2*4+1][c] = wv.y;
            Bs[s2*4+2][c] = wv.z; Bs[s2*4+3][c] = wv.w;
        }
        __syncthreads();
#pragma unroll
        for (int kk = 0; kk < 16; kk++) {
            float a[8], b[4];
            LD4(a,   &As[kk][ry*8]);
            LD4(a+4, &As[kk][ry*8+4]);
            LD4(b,   &Bs[kk][cx*4]);
#pragma unroll
            for (int i = 0; i < 8; i++)
#pragma unroll
                for (int j = 0; j < 4; j++) acc[i][j] += a[i]*b[j];
        }
        __syncthreads();
    }
#pragma unroll
    for (int i = 0; i < 8; i++) {
        *(float4*)&y[(size_t)(m0 + ry*8 + i)*DD + n0 + cx*4] =
            make_float4(acc[i][0], acc[i][1], acc[i][2], acc[i][3]);
    }
}

// ---------------------------------------------------------------------------
extern "C" void kernel_launch(void* const* d_in, const int* in_sizes, int n_in,
                              void* d_out, int out_size)
{
    const float* x  = (const float*)d_in[0];
    const float* Wq = (const float*)d_in[1];
    const float* Wk = (const float*)d_in[2];
    const float* Wv = (const float*)d_in[3];
    const float* Wo = (const float*)d_in[4];
    float* y = (float*)d_out;

    const int attn_smem = 4 * 64 * 68 * sizeof(float);  // 69632 B
    cudaFuncSetAttribute(attn_kernel,
                         cudaFuncAttributeMaxDynamicSharedMemorySize, attn_smem);

    qkv_kernel<<<dim3(MM/128, 48), 256>>>(x, Wq, Wk, Wv);
    attn_kernel<<<dim3(SS/64, BB*HH), 256, attn_smem>>>();
    oproj_kernel<<<dim3(MM/128, DD/64), 256>>>(Wo, y);
}

// round 2
// speedup vs baseline: 1.0045x; 1.0045x over previous
#include <cuda_runtime.h>
#include <cuda_bf16.h>

#define BB 4
#define SS 2048
#define DD 1024
#define HH 16
#define HDD 64
#define MM (BB*SS)   // 8192

// Scratch (allocation-free rule: __device__ globals)
__device__ float g_q[(size_t)BB*HH*SS*HDD];   // [bh][s][e] 32MB
__device__ float g_k[(size_t)BB*HH*SS*HDD];
__device__ float g_v[(size_t)BB*HH*SS*HDD];
__device__ float g_c[(size_t)MM*DD];          // attn out, concat layout [b,s,D]

#define LD4(dst, ptr) { float4 _t = *(const float4*)(ptr); \
    (dst)[0]=_t.x; (dst)[1]=_t.y; (dst)[2]=_t.z; (dst)[3]=_t.w; }

// ---------------------------------------------------------------------------
// Kernel 1: QKV projection. C[row, (which,h,e)] = sum_d x[row,d]*W[h,d,e]
// BM=128, BN=64 (= one head of one tensor), BK=16, 256 thr, 8x4 microtile.
// ---------------------------------------------------------------------------
__global__ __launch_bounds__(256) void qkv_kernel(
    const float* __restrict__ x, const float* __restrict__ Wq,
    const float* __restrict__ Wk, const float* __restrict__ Wv)
{
    __shared__ float As[16][132];   // [k][m], pad 132 (bank rot 4)
    __shared__ float Bs[16][68];    // [k][n], pad 68

    const int rt = blockIdx.x;          // row tile (128 rows)
    const int ct = blockIdx.y;          // 0..47: which*16 + h
    const int which = ct >> 4, h = ct & 15;
    const float* W = (which == 0 ? Wq : which == 1 ? Wk : Wv) + (size_t)h*DD*HDD;
    float* outbuf  = (which == 0 ? g_q : which == 1 ? g_k : g_v);

    const int tid = threadIdx.x;
    const int ry = tid >> 4;            // 0..15 -> rows ry*8..ry*8+7
    const int cx = tid & 15;            // cols cx*4..cx*4+3
    const int m0 = rt * 128;
    const int lr = tid >> 2, sg = tid & 3;

    float acc[8][4];
#pragma unroll
    for (int i = 0; i < 8; i++)
#pragma unroll
        for (int j = 0; j < 4; j++) acc[i][j] = 0.f;

    for (int k0 = 0; k0 < DD; k0 += 16) {
        // A tile: 128x16, stored transposed As[k][m]
#pragma unroll
        for (int hf = 0; hf < 2; hf++) {
            int row = lr + hf*64;
            float4 av = *(const float4*)&x[(size_t)(m0+row)*DD + k0 + sg*4];
            As[sg*4+0][row] = av.x; As[sg*4+1][row] = av.y;
            As[sg*4+2][row] = av.z; As[sg*4+3][row] = av.w;
        }
        // B tile: 16x64, direct
        {
            int kk = tid >> 4, s2 = tid & 15;
            float4 bv = *(const float4*)&W[(size_t)(k0+kk)*HDD + s2*4];
            *(float4*)&Bs[kk][s2*4] = bv;
        }
        __syncthreads();
#pragma unroll
        for (int kk = 0; kk < 16; kk++) {
            float a[8], b[4];
            LD4(a,   &As[kk][ry*8]);
            LD4(a+4, &As[kk][ry*8+4]);
            LD4(b,   &Bs[kk][cx*4]);
#pragma unroll
            for (int i = 0; i < 8; i++)
#pragma unroll
                for (int j = 0; j < 4; j++) acc[i][j] += a[i]*b[j];
        }
        __syncthreads();
    }
    // Epilogue: out[((b*H+h)*S+s)*HD + e]
#pragma unroll
    for (int i = 0; i < 8; i++) {
        int r = m0 + ry*8 + i;
        int b = r >> 11, s = r & (SS-1);
        float4 v4 = make_float4(acc[i][0], acc[i][1], acc[i][2], acc[i][3]);
        *(float4*)&outbuf[((size_t)(b*HH + h)*SS + s)*HDD + cx*4] = v4;
    }
}

// ---------------------------------------------------------------------------
// Kernel 2: flash-style causal attention. CTA = (qtile of 64 rows, bh).
// 256 threads; score/PV microtile 4x4 per thread. K stored transposed.
// ---------------------------------------------------------------------------
__global__ __launch_bounds__(256) void attn_kernel() {
    extern __shared__ float sm[];
    float* Qs  = sm;                 // [64][68]  (q rows, d cols), pre-scaled
    float* Kts = Qs  + 64*68;        // [64][68]  (d rows, k cols) TRANSPOSED
    float* Vs  = Kts + 64*68;        // [64][68]  (k rows, d cols)
    float* Ps  = Vs  + 64*68;        // [64][68]  (q rows, k cols)

    const int qt = blockIdx.x;       // 0..31
    const int bh = blockIdx.y;       // 0..63
    const int b = bh >> 4, h = bh & 15;
    const float* qb = g_q + (size_t)bh*SS*HDD;
    const float* kb = g_k + (size_t)bh*SS*HDD;
    const float* vb = g_v + (size_t)bh*SS*HDD;

    const int tid = threadIdx.x;
    const int ry = tid >> 4, cx = tid & 15;

    // Load Q tile, pre-scaled by 1/sqrt(HD)=0.125
    for (int t = tid; t < 64*16; t += 256) {
        int row = t >> 4, sc = t & 15;
        float4 qv = *(const float4*)&qb[(size_t)(qt*64+row)*HDD + sc*4];
        qv.x *= 0.125f; qv.y *= 0.125f; qv.z *= 0.125f; qv.w *= 0.125f;
        *(float4*)&Qs[row*68 + sc*4] = qv;
    }

    float m[4], l[4], o[4][4];
#pragma unroll
    for (int i = 0; i < 4; i++) {
        m[i] = -1e30f; l[i] = 0.f;
#pragma unroll
        for (int j = 0; j < 4; j++) o[i][j] = 0.f;
    }

    for (int kt = 0; kt <= qt; kt++) {
        __syncthreads();  // prior reads of Kts/Vs/Ps done; also fences Q stores (1st iter)
        for (int t = tid; t < 64*16; t += 256) {
            int row = t >> 4, sc = t & 15;  // row = k index
            float4 kv = *(const float4*)&kb[(size_t)(kt*64+row)*HDD + sc*4];
            Kts[(sc*4+0)*68 + row] = kv.x;
            Kts[(sc*4+1)*68 + row] = kv.y;
            Kts[(sc*4+2)*68 + row] = kv.z;
            Kts[(sc*4+3)*68 + row] = kv.w;
            float4 vv = *(const float4*)&vb[(size_t)(kt*64+row)*HDD + sc*4];
            *(float4*)&Vs[row*68 + sc*4] = vv;
        }
        __syncthreads();

        // Scores: s[i][j] = sum_d Q[r_i][d] * K[c_j][d]
        float s[4][4];
#pragma unroll
        for (int i = 0; i < 4; i++)
#pragma unroll
            for (int j = 0; j < 4; j++) s[i][j] = 0.f;

#pragma unroll 8
        for (int d = 0; d < 64; d += 4) {
            float a[4][4], bq[4][4];
#pragma unroll
            for (int i = 0; i < 4; i++) LD4(a[i],  &Qs[(ry*4+i)*68 + d]);
#pragma unroll
            for (int u = 0; u < 4; u++) LD4(bq[u], &Kts[(d+u)*68 + cx*4]);
#pragma unroll
            for (int i = 0; i < 4; i++)
#pragma unroll
                for (int u = 0; u < 4; u++)
#pragma unroll
                    for (int j = 0; j < 4; j++)
                        s[i][j] += a[i][u] * bq[u][j];
        }

        // Causal mask on diagonal tile
        if (kt == qt) {
#pragma unroll
            for (int i = 0; i < 4; i++)
#pragma unroll
                for (int j = 0; j < 4; j++)
                    if (cx*4+j > ry*4+i) s[i][j] = -1e30f;
        }

        // Online softmax. Row group = 16 lanes (same ry), shuffle reduce.
#pragma unroll
        for (int i = 0; i < 4; i++) {
            float rm = fmaxf(fmaxf(s[i][0], s[i][1]), fmaxf(s[i][2], s[i][3]));
#pragma unroll
            for (int off = 8; off >= 1; off >>= 1)
                rm = fmaxf(rm, __shfl_xor_sync(0xffffffffu, rm, off));
            float mnew = fmaxf(m[i], rm);
            float corr = __expf(m[i] - mnew);
            float rs = 0.f;
#pragma unroll
            for (int j = 0; j < 4; j++) { s[i][j] = __expf(s[i][j] - mnew); rs += s[i][j]; }
#pragma unroll
            for (int off = 8; off >= 1; off >>= 1)
                rs += __shfl_xor_sync(0xffffffffu, rs, off);
            l[i] = l[i]*corr + rs;
            m[i] = mnew;
#pragma unroll
            for (int j = 0; j < 4; j++) o[i][j] *= corr;
            *(float4*)&Ps[(ry*4+i)*68 + cx*4] =
                make_float4(s[i][0], s[i][1], s[i][2], s[i][3]);
        }
        __syncthreads();

        // O += P @ V
#pragma unroll 8
        for (int kk = 0; kk < 64; kk += 4) {
            float p[4][4], vv[4][4];
#pragma unroll
            for (int i = 0; i < 4; i++) LD4(p[i],  &Ps[(ry*4+i)*68 + kk]);
#pragma unroll
            for (int u = 0; u < 4; u++) LD4(vv[u], &Vs[(kk+u)*68 + cx*4]);
#pragma unroll
            for (int i = 0; i < 4; i++)
#pragma unroll
                for (int u = 0; u < 4; u++)
#pragma unroll
                    for (int j = 0; j < 4; j++)
                        o[i][j] += p[i][u] * vv[u][j];
        }
    }

    // Epilogue into concat layout [b, s, h*64 + e]
#pragma unroll
    for (int i = 0; i < 4; i++) {
        float inv = 1.0f / l[i];
        size_t grow = (size_t)(b*SS + qt*64 + ry*4 + i);
        *(float4*)&g_c[grow*DD + h*64 + cx*4] =
            make_float4(o[i][0]*inv, o[i][1]*inv, o[i][2]*inv, o[i][3]*inv);
    }
}

// ---------------------------------------------------------------------------
// Kernel 3: output projection y = C @ W_O^T. Same tiling as qkv_kernel;
// B operand transposed from W_O (Bs[k][n] = W_O[n][k]).
// ---------------------------------------------------------------------------
__global__ __launch_bounds__(256) void oproj_kernel(
    const float* __restrict__ Wo, float* __restrict__ y)
{
    __shared__ float As[16][132];
    __shared__ float Bs[16][68];

    const int rt = blockIdx.x, ctn = blockIdx.y;
    const int m0 = rt * 128, n0 = ctn * 64;
    const int tid = threadIdx.x;
    const int ry = tid >> 4, cx = tid & 15;
    const int lr = tid >> 2, sg = tid & 3;

    float acc[8][4];
#pragma unroll
    for (int i = 0; i < 8; i++)
#pragma unroll
        for (int j = 0; j < 4; j++) acc[i][j] = 0.f;

    for (int k0 = 0; k0 < DD; k0 += 16) {
#pragma unroll
        for (int hf = 0; hf < 2; hf++) {
            int row = lr + hf*64;
            float4 av = *(const float4*)&g_c[(size_t)(m0+row)*DD + k0 + sg*4];
            As[sg*4+0][row] = av.x; As[sg*4+1][row] = av.y;
            As[sg*4+2][row] = av.z; As[sg*4+3][row] = av.w;
        }
        {
            int c = tid >> 2, s2 = tid & 3;   // c = output col, s2*4.. = k seg
            float4 wv = *(const float4*)&Wo[(size_t)(n0+c)*DD + k0 + s2*4];
            Bs[s2*4+0][c] = wv.x; Bs[s2*4+1][c] = wv.y;
            Bs[s2*4+2][c] = wv.z; Bs[s2*4+3][c] = wv.w;
        }
        __syncthreads();
#pragma unroll
        for (int kk = 0; kk < 16; kk++) {
            float a[8], b[4];
            LD4(a,   &As[kk][ry*8]);
            LD4(a+4, &As[kk][ry*8+4]);
            LD4(b,   &Bs[kk][cx*4]);
#pragma unroll
            for (int i = 0; i < 8; i++)
#pragma unroll
                for (int j = 0; j < 4; j++) acc[i][j] += a[i]*b[j];
        }
        __syncthreads();
    }
#pragma unroll
    for (int i = 0; i < 8; i++) {
        *(float4*)&y[(size_t)(m0 + ry*8 + i)*DD + n0 + cx*4] =
            make_float4(acc[i][0], acc[i][1], acc[i][2], acc[i][3]);
    }
}

// ---------------------------------------------------------------------------
extern "C" void kernel_launch(void* const* d_in, const int* in_sizes, int n_in,
                              void* d_out, int out_size)
{
    const float* x  = (const float*)d_in[0];
    const float* Wq = (const float*)d_in[1];
    const float* Wk = (const float*)d_in[2];
    const float* Wv = (const float*)d_in[3];
    const float* Wo = (const float*)d_in[4];
    float* y = (float*)d_out;

    const int attn_smem = 4 * 64 * 68 * sizeof(float);  // 69632 B
    cudaFuncSetAttribute(attn_kernel,
                         cudaFuncAttributeMaxDynamicSharedMemorySize, attn_smem);

    qkv_kernel<<<dim3(MM/128, 48), 256>>>(x, Wq, Wk, Wv);
    attn_kernel<<<dim3(SS/64, BB*HH), 256, attn_smem>>>();
    oproj_kernel<<<dim3(MM/128, DD/64), 256>>>(Wo, y);
}

// round 8
// speedup vs baseline: 1.0499x; 1.0452x over previous
#include <cuda_runtime.h>
#include <cuda_bf16.h>
#include <cstdint>

#define BB 4
#define SS 2048
#define DD 1024
#define HH 16
#define HDD 64
#define MM (BB*SS)   // 8192

// Scratch (allocation-free rule: __device__ globals)
__device__ float g_q[(size_t)BB*HH*SS*HDD];   // [bh][s][e] 32MB
__device__ float g_k[(size_t)BB*HH*SS*HDD];
__device__ float g_v[(size_t)BB*HH*SS*HDD];
__device__ float g_c[(size_t)MM*DD];          // attn out, concat layout [b,s,D]

#define LD4(dst, ptr) { float4 _t = *(const float4*)(ptr); \
    (dst)[0]=_t.x; (dst)[1]=_t.y; (dst)[2]=_t.z; (dst)[3]=_t.w; }

// ---------------------------------------------------------------------------
// Kernel 1: QKV projection (FFMA; byte-identical to R1 passing version).
// ---------------------------------------------------------------------------
__global__ __launch_bounds__(256) void qkv_kernel(
    const float* __restrict__ x, const float* __restrict__ Wq,
    const float* __restrict__ Wk, const float* __restrict__ Wv)
{
    __shared__ float As[16][132];   // [k][m], pad 132 (bank rot 4)
    __shared__ float Bs[16][68];    // [k][n], pad 68

    const int rt = blockIdx.x;          // row tile (128 rows)
    const int ct = blockIdx.y;          // 0..47: which*16 + h
    const int which = ct >> 4, h = ct & 15;
    const float* W = (which == 0 ? Wq : which == 1 ? Wk : Wv) + (size_t)h*DD*HDD;
    float* outbuf  = (which == 0 ? g_q : which == 1 ? g_k : g_v);

    const int tid = threadIdx.x;
    const int ry = tid >> 4;            // 0..15 -> rows ry*8..ry*8+7
    const int cx = tid & 15;            // cols cx*4..cx*4+3
    const int m0 = rt * 128;
    const int lr = tid >> 2, sg = tid & 3;

    float acc[8][4];
#pragma unroll
    for (int i = 0; i < 8; i++)
#pragma unroll
        for (int j = 0; j < 4; j++) acc[i][j] = 0.f;

    for (int k0 = 0; k0 < DD; k0 += 16) {
        // A tile: 128x16, stored transposed As[k][m]
#pragma unroll
        for (int hf = 0; hf < 2; hf++) {
            int row = lr + hf*64;
            float4 av = *(const float4*)&x[(size_t)(m0+row)*DD + k0 + sg*4];
            As[sg*4+0][row] = av.x; As[sg*4+1][row] = av.y;
            As[sg*4+2][row] = av.z; As[sg*4+3][row] = av.w;
        }
        // B tile: 16x64, direct
        {
            int kk = tid >> 4, s2 = tid & 15;
            float4 bv = *(const float4*)&W[(size_t)(k0+kk)*HDD + s2*4];
            *(float4*)&Bs[kk][s2*4] = bv;
        }
        __syncthreads();
#pragma unroll
        for (int kk = 0; kk < 16; kk++) {
            float a[8], b[4];
            LD4(a,   &As[kk][ry*8]);
            LD4(a+4, &As[kk][ry*8+4]);
            LD4(b,   &Bs[kk][cx*4]);
#pragma unroll
            for (int i = 0; i < 8; i++)
#pragma unroll
                for (int j = 0; j < 4; j++) acc[i][j] += a[i]*b[j];
        }
        __syncthreads();
    }
    // Epilogue: out[((b*H+h)*S+s)*HD + e]
#pragma unroll
    for (int i = 0; i < 8; i++) {
        int r = m0 + ry*8 + i;
        int b = r >> 11, s = r & (SS-1);
        float4 v4 = make_float4(acc[i][0], acc[i][1], acc[i][2], acc[i][3]);
        *(float4*)&outbuf[((size_t)(b*HH + h)*SS + s)*HDD + cx*4] = v4;
    }
}

// ---------------------------------------------------------------------------
// Kernel 2: flash-style causal attention (FFMA; byte-identical to R1).
// ---------------------------------------------------------------------------
__global__ __launch_bounds__(256) void attn_kernel() {
    extern __shared__ float sm[];
    float* Qs  = sm;                 // [64][68]  (q rows, d cols), pre-scaled
    float* Kts = Qs  + 64*68;        // [64][68]  (d rows, k cols) TRANSPOSED
    float* Vs  = Kts + 64*68;        // [64][68]  (k rows, d cols)
    float* Ps  = Vs  + 64*68;        // [64][68]  (q rows, k cols)

    const int qt = blockIdx.x;       // 0..31
    const int bh = blockIdx.y;       // 0..63
    const int b = bh >> 4, h = bh & 15;
    const float* qb = g_q + (size_t)bh*SS*HDD;
    const float* kb = g_k + (size_t)bh*SS*HDD;
    const float* vb = g_v + (size_t)bh*SS*HDD;

    const int tid = threadIdx.x;
    const int ry = tid >> 4, cx = tid & 15;

    // Load Q tile, pre-scaled by 1/sqrt(HD)=0.125
    for (int t = tid; t < 64*16; t += 256) {
        int row = t >> 4, sc = t & 15;
        float4 qv = *(const float4*)&qb[(size_t)(qt*64+row)*HDD + sc*4];
        qv.x *= 0.125f; qv.y *= 0.125f; qv.z *= 0.125f; qv.w *= 0.125f;
        *(float4*)&Qs[row*68 + sc*4] = qv;
    }

    float m[4], l[4], o[4][4];
#pragma unroll
    for (int i = 0; i < 4; i++) {
        m[i] = -1e30f; l[i] = 0.f;
#pragma unroll
        for (int j = 0; j < 4; j++) o[i][j] = 0.f;
    }

    for (int kt = 0; kt <= qt; kt++) {
        __syncthreads();  // prior reads of Kts/Vs/Ps done; also fences Q stores (1st iter)
        for (int t = tid; t < 64*16; t += 256) {
            int row = t >> 4, sc = t & 15;  // row = k index
            float4 kv = *(const float4*)&kb[(size_t)(kt*64+row)*HDD + sc*4];
            Kts[(sc*4+0)*68 + row] = kv.x;
            Kts[(sc*4+1)*68 + row] = kv.y;
            Kts[(sc*4+2)*68 + row] = kv.z;
            Kts[(sc*4+3)*68 + row] = kv.w;
            float4 vv = *(const float4*)&vb[(size_t)(kt*64+row)*HDD + sc*4];
            *(float4*)&Vs[row*68 + sc*4] = vv;
        }
        __syncthreads();

        // Scores: s[i][j] = sum_d Q[r_i][d] * K[c_j][d]
        float s[4][4];
#pragma unroll
        for (int i = 0; i < 4; i++)
#pragma unroll
            for (int j = 0; j < 4; j++) s[i][j] = 0.f;

#pragma unroll 8
        for (int d = 0; d < 64; d += 4) {
            float a[4][4], bq[4][4];
#pragma unroll
            for (int i = 0; i < 4; i++) LD4(a[i],  &Qs[(ry*4+i)*68 + d]);
#pragma unroll
            for (int u = 0; u < 4; u++) LD4(bq[u], &Kts[(d+u)*68 + cx*4]);
#pragma unroll
            for (int i = 0; i < 4; i++)
#pragma unroll
                for (int u = 0; u < 4; u++)
#pragma unroll
                    for (int j = 0; j < 4; j++)
                        s[i][j] += a[i][u] * bq[u][j];
        }

        // Causal mask on diagonal tile
        if (kt == qt) {
#pragma unroll
            for (int i = 0; i < 4; i++)
#pragma unroll
                for (int j = 0; j < 4; j++)
                    if (cx*4+j > ry*4+i) s[i][j] = -1e30f;
        }

        // Online softmax. Row group = 16 lanes (same ry), shuffle reduce.
#pragma unroll
        for (int i = 0; i < 4; i++) {
            float rm = fmaxf(fmaxf(s[i][0], s[i][1]), fmaxf(s[i][2], s[i][3]));
#pragma unroll
            for (int off = 8; off >= 1; off >>= 1)
                rm = fmaxf(rm, __shfl_xor_sync(0xffffffffu, rm, off));
            float mnew = fmaxf(m[i], rm);
            float corr = __expf(m[i] - mnew);
            float rs = 0.f;
#pragma unroll
            for (int j = 0; j < 4; j++) { s[i][j] = __expf(s[i][j] - mnew); rs += s[i][j]; }
#pragma unroll
            for (int off = 8; off >= 1; off >>= 1)
                rs += __shfl_xor_sync(0xffffffffu, rs, off);
            l[i] = l[i]*corr + rs;
            m[i] = mnew;
#pragma unroll
            for (int j = 0; j < 4; j++) o[i][j] *= corr;
            *(float4*)&Ps[(ry*4+i)*68 + cx*4] =
                make_float4(s[i][0], s[i][1], s[i][2], s[i][3]);
        }
        __syncthreads();

        // O += P @ V
#pragma unroll 8
        for (int kk = 0; kk < 64; kk += 4) {
            float p[4][4], vv[4][4];
#pragma unroll
            for (int i = 0; i < 4; i++) LD4(p[i],  &Ps[(ry*4+i)*68 + kk]);
#pragma unroll
            for (int u = 0; u < 4; u++) LD4(vv[u], &Vs[(kk+u)*68 + cx*4]);
#pragma unroll
            for (int i = 0; i < 4; i++)
#pragma unroll
                for (int u = 0; u < 4; u++)
#pragma unroll
                    for (int j = 0; j < 4; j++)
                        o[i][j] += p[i][u] * vv[u][j];
        }
    }

    // Epilogue into concat layout [b, s, h*64 + e]
#pragma unroll
    for (int i = 0; i < 4; i++) {
        float inv = 1.0f / l[i];
        size_t grow = (size_t)(b*SS + qt*64 + ry*4 + i);
        *(float4*)&g_c[grow*DD + h*64 + cx*4] =
            make_float4(o[i][0]*inv, o[i][1]*inv, o[i][2]*inv, o[i][3]*inv);
    }
}

// ---------------------------------------------------------------------------
// Kernel 3 (EXPERIMENT): output projection via tf32 mma.sync.
// Plain kernel (no template), CTA 64x64, BK=16, 256 thr, 8 warps (4m x 2n),
// warp tile 16x32 -> 16 accs/thread (~50 regs). y = C @ Wo^T.
// ---------------------------------------------------------------------------
__device__ __forceinline__ uint32_t f2tf32(float f) {
    uint32_t u;
    asm("cvt.rna.tf32.f32 %0, %1;" : "=r"(u) : "f"(f));
    return u;
}

#define MMA_TF32(c, a, b0, b1) \
    asm volatile("mma.sync.aligned.m16n8k8.row.col.f32.tf32.tf32.f32 " \
        "{%0,%1,%2,%3}, {%4,%5,%6,%7}, {%8,%9}, {%0,%1,%2,%3};" \
        : "+f"((c)[0]), "+f"((c)[1]), "+f"((c)[2]), "+f"((c)[3]) \
        : "r"((a)[0]), "r"((a)[1]), "r"((a)[2]), "r"((a)[3]), "r"(b0), "r"(b1))

#define APAD 20
#define BPAD 136

__global__ __launch_bounds__(256) void oproj_mma(
    const float* __restrict__ Wo, float* __restrict__ Y)
{
    __shared__ uint32_t As[64 * APAD];    // [m][k] tf32 bits
    __shared__ uint32_t Bs[16 * BPAD];    // [k][n] tf32 bits

    const int tid = threadIdx.x;
    const int wid = tid >> 5, lane = tid & 31;
    const int m0w = (wid & 3) * 16, n0w = (wid >> 2) * 32;
    const int m0 = blockIdx.x * 64, n0 = blockIdx.y * 64;
    const int lr = lane >> 2, lc = lane & 3;

    float acc[4][4];
#pragma unroll
    for (int nt = 0; nt < 4; nt++)
#pragma unroll
        for (int i = 0; i < 4; i++) acc[nt][i] = 0.f;

    const int arow = tid >> 2, akseg = (tid & 3) * 4;

    for (int k0 = 0; k0 < DD; k0 += 16) {
        // A tile: 64 x 16 f32 from g_c (one float4 per thread)
        {
            float4 v = *(const float4*)&g_c[(size_t)(m0 + arow) * DD + k0 + akseg];
            uint32_t* d = &As[arow * APAD + akseg];
            d[0] = f2tf32(v.x); d[1] = f2tf32(v.y);
            d[2] = f2tf32(v.z); d[3] = f2tf32(v.w);
        }
        // B tile: Wo rows are output cols (y = C @ Wo^T) -> k-major Bs[k][n]
        {
            float4 v = *(const float4*)&Wo[(size_t)(n0 + arow) * DD + k0 + akseg];
            Bs[(akseg + 0) * BPAD + arow] = f2tf32(v.x);
            Bs[(akseg + 1) * BPAD + arow] = f2tf32(v.y);
            Bs[(akseg + 2) * BPAD + arow] = f2tf32(v.z);
            Bs[(akseg + 3) * BPAD + arow] = f2tf32(v.w);
        }
        __syncthreads();

#pragma unroll
        for (int ks = 0; ks < 2; ks++) {
            const int k8 = ks * 8;
            uint32_t a[4];
            {
                const int r = (m0w + lr) * APAD;
                a[0] = As[r + k8 + lc];
                a[1] = As[r + 8 * APAD + k8 + lc];
                a[2] = As[r + k8 + lc + 4];
                a[3] = As[r + 8 * APAD + k8 + lc + 4];
            }
#pragma unroll
            for (int nt = 0; nt < 4; nt++) {
                const int n = n0w + nt * 8 + lr;
                uint32_t b0 = Bs[(k8 + lc) * BPAD + n];
                uint32_t b1 = Bs[(k8 + lc + 4) * BPAD + n];
                MMA_TF32(acc[nt], a, b0, b1);
            }
        }
        __syncthreads();
    }

#pragma unroll
    for (int half = 0; half < 2; half++) {       // c01 (row lr) / c23 (row lr+8)
        const int m = m0 + m0w + lr + half * 8;
#pragma unroll
        for (int nt = 0; nt < 4; nt++) {
            const int e = n0w + nt * 8 + 2 * lc;
            *(float2*)&Y[(size_t)m * DD + n0 + e] =
                make_float2(acc[nt][half * 2], acc[nt][half * 2 + 1]);
        }
    }
}

// ---------------------------------------------------------------------------
extern "C" void kernel_launch(void* const* d_in, const int* in_sizes, int n_in,
                              void* d_out, int out_size)
{
    const float* x  = (const float*)d_in[0];
    const float* Wq = (const float*)d_in[1];
    const float* Wk = (const float*)d_in[2];
    const float* Wv = (const float*)d_in[3];
    const float* Wo = (const float*)d_in[4];
    float* y = (float*)d_out;

    const int attn_smem = 4 * 64 * 68 * sizeof(float);  // 69632
    cudaFuncSetAttribute(attn_kernel,
                         cudaFuncAttributeMaxDynamicSharedMemorySize, attn_smem);

    qkv_kernel<<<dim3(MM/128, 48), 256>>>(x, Wq, Wk, Wv);
    attn_kernel<<<dim3(SS/64, BB*HH), 256, attn_smem>>>();
    oproj_mma<<<dim3(MM/64, DD/64), 256>>>(Wo, y);
}

// round 9
// speedup vs baseline: 1.3851x; 1.3193x over previous
#include <cuda_runtime.h>
#include <cuda_bf16.h>
#include <cstdint>

#define BB 4
#define SS 2048
#define DD 1024
#define HH 16
#define HDD 64
#define MM (BB*SS)   // 8192

// Scratch (allocation-free rule: __device__ globals)
__device__ float g_q[(size_t)BB*HH*SS*HDD];   // [bh][s][e] 32MB
__device__ float g_k[(size_t)BB*HH*SS*HDD];
__device__ float g_v[(size_t)BB*HH*SS*HDD];
__device__ float g_c[(size_t)MM*DD];          // attn out, concat layout [b,s,D]

#define LD4(dst, ptr) { float4 _t = *(const float4*)(ptr); \
    (dst)[0]=_t.x; (dst)[1]=_t.y; (dst)[2]=_t.z; (dst)[3]=_t.w; }

__device__ __forceinline__ uint32_t f2tf32(float f) {
    uint32_t u;
    asm("cvt.rna.tf32.f32 %0, %1;" : "=r"(u) : "f"(f));
    return u;
}

#define MMA_TF32(c, a, b0, b1) \
    asm volatile("mma.sync.aligned.m16n8k8.row.col.f32.tf32.tf32.f32 " \
        "{%0,%1,%2,%3}, {%4,%5,%6,%7}, {%8,%9}, {%0,%1,%2,%3};" \
        : "+f"((c)[0]), "+f"((c)[1]), "+f"((c)[2]), "+f"((c)[3]) \
        : "r"((a)[0]), "r"((a)[1]), "r"((a)[2]), "r"((a)[3]), "r"(b0), "r"(b1))

// ---------------------------------------------------------------------------
// Kernel 1 (NEW): QKV projection via tf32 mma.sync.
// Plain kernel, CTA 128x64 (one head of one of {Wq,Wk,Wv} per n-block),
// BK=32, 512 thr / 16 warps (8m x 2n), warp tile 16x32 -> 16 accs/thread.
// B loaded DIRECTLY (e contiguous in W[h][k][e]) — no gather, no template.
// ---------------------------------------------------------------------------
#define QAPAD 36   // A word stride (32 + 4)
#define QBPAD 72   // B word stride (64 + 8)

__global__ __launch_bounds__(512) void qkv_mma(
    const float* __restrict__ x,  const float* __restrict__ Wq,
    const float* __restrict__ Wk, const float* __restrict__ Wv)
{
    __shared__ uint32_t As[128 * QAPAD];   // [m][k] tf32 bits
    __shared__ uint32_t Bs[32 * QBPAD];    // [k][n] tf32 bits

    const int tid = threadIdx.x;
    const int wid = tid >> 5, lane = tid & 31;
    const int m0w = (wid & 7) * 16, n0w = (wid >> 3) * 32;
    const int m0 = blockIdx.x * 128;
    const int ct = blockIdx.y;                 // 0..47: which*16 + h
    const int which = ct >> 4, h = ct & 15;
    const float* W = (which == 0 ? Wq : which == 1 ? Wk : Wv)
                   + (size_t)h * DD * HDD;
    float* ob = (which == 0) ? g_q : (which == 1) ? g_k : g_v;

    const int lr = lane >> 2, lc = lane & 3;

    float acc[4][4];
#pragma unroll
    for (int nt = 0; nt < 4; nt++)
#pragma unroll
        for (int i = 0; i < 4; i++) acc[nt][i] = 0.f;

    const int arow = tid >> 2, akseg = (tid & 3) * 8;  // A loader
    const int bkk = tid >> 4, be4 = tid & 15;          // B loader

    for (int k0 = 0; k0 < DD; k0 += 32) {
        // ---- A tile: 128 x 32 f32 (two float4 per thread, coalesced) ----
        {
            const float* ap = &x[(size_t)(m0 + arow) * DD + k0 + akseg];
            float4 v0 = *(const float4*)ap;
            float4 v1 = *(const float4*)(ap + 4);
            uint32_t* d = &As[arow * QAPAD + akseg];
            *(uint4*)d = make_uint4(f2tf32(v0.x), f2tf32(v0.y),
                                    f2tf32(v0.z), f2tf32(v0.w));
            *(uint4*)(d + 4) = make_uint4(f2tf32(v1.x), f2tf32(v1.y),
                                          f2tf32(v1.z), f2tf32(v1.w));
        }
        // ---- B tile: 32 k-rows x 64 n (direct, coalesced: e contiguous) ----
        {
            float4 v = *(const float4*)&W[(size_t)(k0 + bkk) * HDD + be4 * 4];
            *(uint4*)&Bs[bkk * QBPAD + be4 * 4] =
                make_uint4(f2tf32(v.x), f2tf32(v.y), f2tf32(v.z), f2tf32(v.w));
        }
        __syncthreads();

#pragma unroll
        for (int ks = 0; ks < 4; ks++) {
            const int k8 = ks * 8;
            uint32_t a[4];
            {
                const int r = (m0w + lr) * QAPAD;
                a[0] = As[r + k8 + lc];
                a[1] = As[r + 8 * QAPAD + k8 + lc];
                a[2] = As[r + k8 + lc + 4];
                a[3] = As[r + 8 * QAPAD + k8 + lc + 4];
            }
#pragma unroll
            for (int nt = 0; nt < 4; nt++) {
                const int n = n0w + nt * 8 + lr;
                uint32_t b0 = Bs[(k8 + lc) * QBPAD + n];
                uint32_t b1 = Bs[(k8 + lc + 4) * QBPAD + n];
                MMA_TF32(acc[nt], a, b0, b1);
            }
        }
        __syncthreads();
    }

    // ---- Epilogue: scatter into [bh][s][e] ----
#pragma unroll
    for (int half = 0; half < 2; half++) {
        const int m = m0 + m0w + lr + half * 8;
        const int b = m >> 11, srow = m & (SS - 1);
        float* dst = ob + ((size_t)(b * HH + h) * SS + srow) * HDD;
#pragma unroll
        for (int nt = 0; nt < 4; nt++) {
            const int e = n0w + nt * 8 + 2 * lc;
            *(float2*)(dst + e) =
                make_float2(acc[nt][half * 2], acc[nt][half * 2 + 1]);
        }
    }
}

// ---------------------------------------------------------------------------
// Kernel 2: flash-style causal attention (FFMA; byte-identical to R1/R7).
// ---------------------------------------------------------------------------
__global__ __launch_bounds__(256) void attn_kernel() {
    extern __shared__ float sm[];
    float* Qs  = sm;                 // [64][68]
    float* Kts = Qs  + 64*68;        // [64][68] transposed
    float* Vs  = Kts + 64*68;        // [64][68]
    float* Ps  = Vs  + 64*68;        // [64][68]

    const int qt = blockIdx.x;
    const int bh = blockIdx.y;
    const int b = bh >> 4, h = bh & 15;
    const float* qb = g_q + (size_t)bh*SS*HDD;
    const float* kb = g_k + (size_t)bh*SS*HDD;
    const float* vb = g_v + (size_t)bh*SS*HDD;

    const int tid = threadIdx.x;
    const int ry = tid >> 4, cx = tid & 15;

    for (int t = tid; t < 64*16; t += 256) {
        int row = t >> 4, sc = t & 15;
        float4 qv = *(const float4*)&qb[(size_t)(qt*64+row)*HDD + sc*4];
        qv.x *= 0.125f; qv.y *= 0.125f; qv.z *= 0.125f; qv.w *= 0.125f;
        *(float4*)&Qs[row*68 + sc*4] = qv;
    }

    float m[4], l[4], o[4][4];
#pragma unroll
    for (int i = 0; i < 4; i++) {
        m[i] = -1e30f; l[i] = 0.f;
#pragma unroll
        for (int j = 0; j < 4; j++) o[i][j] = 0.f;
    }

    for (int kt = 0; kt <= qt; kt++) {
        __syncthreads();
        for (int t = tid; t < 64*16; t += 256) {
            int row = t >> 4, sc = t & 15;
            float4 kv = *(const float4*)&kb[(size_t)(kt*64+row)*HDD + sc*4];
            Kts[(sc*4+0)*68 + row] = kv.x;
            Kts[(sc*4+1)*68 + row] = kv.y;
            Kts[(sc*4+2)*68 + row] = kv.z;
            Kts[(sc*4+3)*68 + row] = kv.w;
            float4 vv = *(const float4*)&vb[(size_t)(kt*64+row)*HDD + sc*4];
            *(float4*)&Vs[row*68 + sc*4] = vv;
        }
        __syncthreads();

        float s[4][4];
#pragma unroll
        for (int i = 0; i < 4; i++)
#pragma unroll
            for (int j = 0; j < 4; j++) s[i][j] = 0.f;

#pragma unroll 8
        for (int d = 0; d < 64; d += 4) {
            float a[4][4], bq[4][4];
#pragma unroll
            for (int i = 0; i < 4; i++) LD4(a[i],  &Qs[(ry*4+i)*68 + d]);
#pragma unroll
            for (int u = 0; u < 4; u++) LD4(bq[u], &Kts[(d+u)*68 + cx*4]);
#pragma unroll
            for (int i = 0; i < 4; i++)
#pragma unroll
                for (int u = 0; u < 4; u++)
#pragma unroll
                    for (int j = 0; j < 4; j++)
                        s[i][j] += a[i][u] * bq[u][j];
        }

        if (kt == qt) {
#pragma unroll
            for (int i = 0; i < 4; i++)
#pragma unroll
                for (int j = 0; j < 4; j++)
                    if (cx*4+j > ry*4+i) s[i][j] = -1e30f;
        }

#pragma unroll
        for (int i = 0; i < 4; i++) {
            float rm = fmaxf(fmaxf(s[i][0], s[i][1]), fmaxf(s[i][2], s[i][3]));
#pragma unroll
            for (int off = 8; off >= 1; off >>= 1)
                rm = fmaxf(rm, __shfl_xor_sync(0xffffffffu, rm, off));
            float mnew = fmaxf(m[i], rm);
            float corr = __expf(m[i] - mnew);
            float rs = 0.f;
#pragma unroll
            for (int j = 0; j < 4; j++) { s[i][j] = __expf(s[i][j] - mnew); rs += s[i][j]; }
#pragma unroll
            for (int off = 8; off >= 1; off >>= 1)
                rs += __shfl_xor_sync(0xffffffffu, rs, off);
            l[i] = l[i]*corr + rs;
            m[i] = mnew;
#pragma unroll
            for (int j = 0; j < 4; j++) o[i][j] *= corr;
            *(float4*)&Ps[(ry*4+i)*68 + cx*4] =
                make_float4(s[i][0], s[i][1], s[i][2], s[i][3]);
        }
        __syncthreads();

#pragma unroll 8
        for (int kk = 0; kk < 64; kk += 4) {
            float p[4][4], vv[4][4];
#pragma unroll
            for (int i = 0; i < 4; i++) LD4(p[i],  &Ps[(ry*4+i)*68 + kk]);
#pragma unroll
            for (int u = 0; u < 4; u++) LD4(vv[u], &Vs[(kk+u)*68 + cx*4]);
#pragma unroll
            for (int i = 0; i < 4; i++)
#pragma unroll
                for (int u = 0; u < 4; u++)
#pragma unroll
                    for (int j = 0; j < 4; j++)
                        o[i][j] += p[i][u] * vv[u][j];
        }
    }

#pragma unroll
    for (int i = 0; i < 4; i++) {
        float inv = 1.0f / l[i];
        size_t grow = (size_t)(b*SS + qt*64 + ry*4 + i);
        *(float4*)&g_c[grow*DD + h*64 + cx*4] =
            make_float4(o[i][0]*inv, o[i][1]*inv, o[i][2]*inv, o[i][3]*inv);
    }
}

// ---------------------------------------------------------------------------
// Kernel 3: output projection via tf32 mma.sync (byte-identical to R7 pass).
// ---------------------------------------------------------------------------
#define APAD 20
#define BPAD 136

__global__ __launch_bounds__(256) void oproj_mma(
    const float* __restrict__ Wo, float* __restrict__ Y)
{
    __shared__ uint32_t As[64 * APAD];    // [m][k] tf32 bits
    __shared__ uint32_t Bs[16 * BPAD];    // [k][n] tf32 bits

    const int tid = threadIdx.x;
    const int wid = tid >> 5, lane = tid & 31;
    const int m0w = (wid & 3) * 16, n0w = (wid >> 2) * 32;
    const int m0 = blockIdx.x * 64, n0 = blockIdx.y * 64;
    const int lr = lane >> 2, lc = lane & 3;

    float acc[4][4];
#pragma unroll
    for (int nt = 0; nt < 4; nt++)
#pragma unroll
        for (int i = 0; i < 4; i++) acc[nt][i] = 0.f;

    const int arow = tid >> 2, akseg = (tid & 3) * 4;

    for (int k0 = 0; k0 < DD; k0 += 16) {
        // A tile: 64 x 16 f32 from g_c (one float4 per thread)
        {
            float4 v = *(const float4*)&g_c[(size_t)(m0 + arow) * DD + k0 + akseg];
            uint32_t* d = &As[arow * APAD + akseg];
            d[0] = f2tf32(v.x); d[1] = f2tf32(v.y);
            d[2] = f2tf32(v.z); d[3] = f2tf32(v.w);
        }
        // B tile: Wo rows are output cols (y = C @ Wo^T) -> k-major Bs[k][n]
        {
            float4 v = *(const float4*)&Wo[(size_t)(n0 + arow) * DD + k0 + akseg];
            Bs[(akseg + 0) * BPAD + arow] = f2tf32(v.x);
            Bs[(akseg + 1) * BPAD + arow] = f2tf32(v.y);
            Bs[(akseg + 2) * BPAD + arow] = f2tf32(v.z);
            Bs[(akseg + 3) * BPAD + arow] = f2tf32(v.w);
        }
        __syncthreads();

#pragma unroll
        for (int ks = 0; ks < 2; ks++) {
            const int k8 = ks * 8;
            uint32_t a[4];
            {
                const int r = (m0w + lr) * APAD;
                a[0] = As[r + k8 + lc];
                a[1] = As[r + 8 * APAD + k8 + lc];
                a[2] = As[r + k8 + lc + 4];
                a[3] = As[r + 8 * APAD + k8 + lc + 4];
            }
#pragma unroll
            for (int nt = 0; nt < 4; nt++) {
                const int n = n0w + nt * 8 + lr;
                uint32_t b0 = Bs[(k8 + lc) * BPAD + n];
                uint32_t b1 = Bs[(k8 + lc + 4) * BPAD + n];
                MMA_TF32(acc[nt], a, b0, b1);
            }
        }
        __syncthreads();
    }

#pragma unroll
    for (int half = 0; half < 2; half++) {
        const int m = m0 + m0w + lr + half * 8;
#pragma unroll
        for (int nt = 0; nt < 4; nt++) {
            const int e = n0w + nt * 8 + 2 * lc;
            *(float2*)&Y[(size_t)m * DD + n0 + e] =
                make_float2(acc[nt][half * 2], acc[nt][half * 2 + 1]);
        }
    }
}

// ---------------------------------------------------------------------------
extern "C" void kernel_launch(void* const* d_in, const int* in_sizes, int n_in,
                              void* d_out, int out_size)
{
    const float* x  = (const float*)d_in[0];
    const float* Wq = (const float*)d_in[1];
    const float* Wk = (const float*)d_in[2];
    const float* Wv = (const float*)d_in[3];
    const float* Wo = (const float*)d_in[4];
    float* y = (float*)d_out;

    const int attn_smem = 4 * 64 * 68 * sizeof(float);  // 69632
    cudaFuncSetAttribute(attn_kernel,
                         cudaFuncAttributeMaxDynamicSharedMemorySize, attn_smem);

    qkv_mma<<<dim3(MM/128, 48), 512>>>(x, Wq, Wk, Wv);
    attn_kernel<<<dim3(SS/64, BB*HH), 256, attn_smem>>>();
    oproj_mma<<<dim3(MM/64, DD/64), 256>>>(Wo, y);
}

// round 10
// speedup vs baseline: 1.8650x; 1.3465x over previous
#include <cuda_runtime.h>
#include <cuda_bf16.h>
#include <cstdint>

#define BB 4
#define SS 2048
#define DD 1024
#define HH 16
#define HDD 64
#define MM (BB*SS)   // 8192

// Scratch (allocation-free rule: __device__ globals)
__device__ float g_q[(size_t)BB*HH*SS*HDD];   // [bh][s][e] 32MB
__device__ float g_k[(size_t)BB*HH*SS*HDD];
__device__ float g_v[(size_t)BB*HH*SS*HDD];
__device__ float g_c[(size_t)MM*DD];          // attn out, concat layout [b,s,D]

__device__ __forceinline__ uint32_t f2tf32(float f) {
    uint32_t u;
    asm("cvt.rna.tf32.f32 %0, %1;" : "=r"(u) : "f"(f));
    return u;
}

__device__ __forceinline__ void split_tf32(float x, uint32_t& hi, uint32_t& lo) {
    hi = f2tf32(x);
    lo = f2tf32(x - __uint_as_float(hi));
}

#define MMA_TF32(c, a, b0, b1) \
    asm volatile("mma.sync.aligned.m16n8k8.row.col.f32.tf32.tf32.f32 " \
        "{%0,%1,%2,%3}, {%4,%5,%6,%7}, {%8,%9}, {%0,%1,%2,%3};" \
        : "+f"((c)[0]), "+f"((c)[1]), "+f"((c)[2]), "+f"((c)[3]) \
        : "r"((a)[0]), "r"((a)[1]), "r"((a)[2]), "r"((a)[3]), "r"(b0), "r"(b1))

// ---------------------------------------------------------------------------
// Kernel 1: QKV projection via tf32 mma.sync (byte-identical to R8 pass).
// ---------------------------------------------------------------------------
#define QAPAD 36
#define QBPAD 72

__global__ __launch_bounds__(512) void qkv_mma(
    const float* __restrict__ x,  const float* __restrict__ Wq,
    const float* __restrict__ Wk, const float* __restrict__ Wv)
{
    __shared__ uint32_t As[128 * QAPAD];
    __shared__ uint32_t Bs[32 * QBPAD];

    const int tid = threadIdx.x;
    const int wid = tid >> 5, lane = tid & 31;
    const int m0w = (wid & 7) * 16, n0w = (wid >> 3) * 32;
    const int m0 = blockIdx.x * 128;
    const int ct = blockIdx.y;
    const int which = ct >> 4, h = ct & 15;
    const float* W = (which == 0 ? Wq : which == 1 ? Wk : Wv)
                   + (size_t)h * DD * HDD;
    float* ob = (which == 0) ? g_q : (which == 1) ? g_k : g_v;

    const int lr = lane >> 2, lc = lane & 3;

    float acc[4][4];
#pragma unroll
    for (int nt = 0; nt < 4; nt++)
#pragma unroll
        for (int i = 0; i < 4; i++) acc[nt][i] = 0.f;

    const int arow = tid >> 2, akseg = (tid & 3) * 8;
    const int bkk = tid >> 4, be4 = tid & 15;

    for (int k0 = 0; k0 < DD; k0 += 32) {
        {
            const float* ap = &x[(size_t)(m0 + arow) * DD + k0 + akseg];
            float4 v0 = *(const float4*)ap;
            float4 v1 = *(const float4*)(ap + 4);
            uint32_t* d = &As[arow * QAPAD + akseg];
            *(uint4*)d = make_uint4(f2tf32(v0.x), f2tf32(v0.y),
                                    f2tf32(v0.z), f2tf32(v0.w));
            *(uint4*)(d + 4) = make_uint4(f2tf32(v1.x), f2tf32(v1.y),
                                          f2tf32(v1.z), f2tf32(v1.w));
        }
        {
            float4 v = *(const float4*)&W[(size_t)(k0 + bkk) * HDD + be4 * 4];
            *(uint4*)&Bs[bkk * QBPAD + be4 * 4] =
                make_uint4(f2tf32(v.x), f2tf32(v.y), f2tf32(v.z), f2tf32(v.w));
        }
        __syncthreads();

#pragma unroll
        for (int ks = 0; ks < 4; ks++) {
            const int k8 = ks * 8;
            uint32_t a[4];
            {
                const int r = (m0w + lr) * QAPAD;
                a[0] = As[r + k8 + lc];
                a[1] = As[r + 8 * QAPAD + k8 + lc];
                a[2] = As[r + k8 + lc + 4];
                a[3] = As[r + 8 * QAPAD + k8 + lc + 4];
            }
#pragma unroll
            for (int nt = 0; nt < 4; nt++) {
                const int n = n0w + nt * 8 + lr;
                uint32_t b0 = Bs[(k8 + lc) * QBPAD + n];
                uint32_t b1 = Bs[(k8 + lc + 4) * QBPAD + n];
                MMA_TF32(acc[nt], a, b0, b1);
            }
        }
        __syncthreads();
    }

#pragma unroll
    for (int half = 0; half < 2; half++) {
        const int m = m0 + m0w + lr + half * 8;
        const int b = m >> 11, srow = m & (SS - 1);
        float* dst = ob + ((size_t)(b * HH + h) * SS + srow) * HDD;
#pragma unroll
        for (int nt = 0; nt < 4; nt++) {
            const int e = n0w + nt * 8 + 2 * lc;
            *(float2*)(dst + e) =
                make_float2(acc[nt][half * 2], acc[nt][half * 2 + 1]);
        }
    }
}

// ---------------------------------------------------------------------------
// Kernel 2 (NEW): flash attention via tf32 mma.sync, transpose-free layout.
// CTA = (64-q-row tile, bh). 128 thr / 4 warps; warp owns 16 q-rows.
// S^T = K·Q^T (A=K natural, B=Q^T built once). 3-term split QK^T (exact
// logits); PV: A=P^T (softmax output layout), B=V natural, plain tf32.
// ---------------------------------------------------------------------------
#define SQ_W 72   // Qt  [d][qrow]   stride (B op: 72 % 32 == 8)
#define SK_W 68   // Ka  [kcol][d]   stride (A op: 68 % 32 == 4)
#define SV_W 72   // Vs  [kcol][d]   stride (B op)
#define SP_W 72   // Pt  [kcol][qrow] stride (A op read is 8lc+lr pattern)

#define OFF_QTH 0
#define OFF_QTL 4608
#define OFF_KAH 9216
#define OFF_KAL 13568
#define OFF_VS  17920
#define OFF_PT  22528
#define OFF_CORR 27136
#define OFF_LROW 27200
#define ATTN_SMEM_WORDS 27264   // * 4 = 109056 bytes

__global__ __launch_bounds__(128) void attn_mma() {
    extern __shared__ uint32_t smw[];
    uint32_t* QtH = smw + OFF_QTH;   // [64 d][72]
    uint32_t* QtL = smw + OFF_QTL;
    uint32_t* KaH = smw + OFF_KAH;   // [64 kcol][68]
    uint32_t* KaL = smw + OFF_KAL;
    uint32_t* Vs  = smw + OFF_VS;    // [64 kcol][72]
    uint32_t* Pt  = smw + OFF_PT;    // [64 kcol][72]
    float* CORR = (float*)(smw + OFF_CORR);  // [64] per-qrow rescale
    float* LROW = (float*)(smw + OFF_LROW);  // [64] final denominators

    const int qt = blockIdx.x, bh = blockIdx.y;
    const int b = bh >> 4, h = bh & 15;
    const float* qb = g_q + (size_t)bh * SS * HDD + (size_t)qt * 64 * HDD;
    const float* kb = g_k + (size_t)bh * SS * HDD;
    const float* vb = g_v + (size_t)bh * SS * HDD;

    const int tid = threadIdx.x, wr = tid >> 5, lane = tid & 31;
    const int lr = lane >> 2, lc = lane & 3;
    const int q0w = wr * 16;

    // ---- Load Q once: scale 0.125, split hi/lo, TRANSPOSE to [d][qrow] ----
#pragma unroll
    for (int i = 0; i < 8; i++) {
        int f4 = tid + i * 128;             // 1024 float4 = 64 rows x 16
        int row = f4 >> 4, c4 = f4 & 15;
        float4 v = *(const float4*)&qb[(size_t)row * HDD + c4 * 4];
        float xv[4] = {v.x, v.y, v.z, v.w};
#pragma unroll
        for (int j = 0; j < 4; j++) {
            uint32_t hi, lo;
            split_tf32(xv[j] * 0.125f, hi, lo);
            QtH[(c4 * 4 + j) * SQ_W + row] = hi;
            QtL[(c4 * 4 + j) * SQ_W + row] = lo;
        }
    }

    float oacc[8][4];
#pragma unroll
    for (int nt = 0; nt < 8; nt++)
#pragma unroll
        for (int i = 0; i < 4; i++) oacc[nt][i] = 0.f;
    float mrow[2][2] = {{-1e30f, -1e30f}, {-1e30f, -1e30f}};
    float lrow[2][2] = {{0.f, 0.f}, {0.f, 0.f}};

    for (int kt = 0; kt <= qt; kt++) {
        __syncthreads();   // K/V/Pt safe to overwrite; also fences Q (kt=0)
        // ---- Load K (split hi/lo) and V (tf32) tiles, natural layout ----
#pragma unroll
        for (int i = 0; i < 8; i++) {
            int f4 = tid + i * 128;
            int row = f4 >> 4, c4 = f4 & 15;
            float4 kv = *(const float4*)&kb[(size_t)(kt * 64 + row) * HDD + c4 * 4];
            uint4 h4, l4;
            split_tf32(kv.x, h4.x, l4.x); split_tf32(kv.y, h4.y, l4.y);
            split_tf32(kv.z, h4.z, l4.z); split_tf32(kv.w, h4.w, l4.w);
            *(uint4*)&KaH[row * SK_W + c4 * 4] = h4;
            *(uint4*)&KaL[row * SK_W + c4 * 4] = l4;
            float4 vv = *(const float4*)&vb[(size_t)(kt * 64 + row) * HDD + c4 * 4];
            *(uint4*)&Vs[row * SV_W + c4 * 4] =
                make_uint4(f2tf32(vv.x), f2tf32(vv.y), f2tf32(vv.z), f2tf32(vv.w));
        }
        __syncthreads();

        // ---- S^T = K · Q^T  (M=64 kcol, N=16 qrow, K=64 d), 3-term ----
        float sacc[4][2][4];
#pragma unroll
        for (int mt = 0; mt < 4; mt++)
#pragma unroll
            for (int nt = 0; nt < 2; nt++)
#pragma unroll
                for (int i = 0; i < 4; i++) sacc[mt][nt][i] = 0.f;

#pragma unroll
        for (int k8 = 0; k8 < 64; k8 += 8) {
            uint32_t bqh[2][2], bql[2][2];
#pragma unroll
            for (int nt = 0; nt < 2; nt++) {
                const int nq = q0w + nt * 8 + lr;
                bqh[nt][0] = QtH[(k8 + lc) * SQ_W + nq];
                bqh[nt][1] = QtH[(k8 + lc + 4) * SQ_W + nq];
                bql[nt][0] = QtL[(k8 + lc) * SQ_W + nq];
                bql[nt][1] = QtL[(k8 + lc + 4) * SQ_W + nq];
            }
#pragma unroll
            for (int mt = 0; mt < 4; mt++) {
                uint32_t ah[4], al[4];
                const int r0 = (mt * 16 + lr) * SK_W, r1 = (mt * 16 + 8 + lr) * SK_W;
                ah[0] = KaH[r0 + k8 + lc];     ah[1] = KaH[r1 + k8 + lc];
                ah[2] = KaH[r0 + k8 + lc + 4]; ah[3] = KaH[r1 + k8 + lc + 4];
                al[0] = KaL[r0 + k8 + lc];     al[1] = KaL[r1 + k8 + lc];
                al[2] = KaL[r0 + k8 + lc + 4]; al[3] = KaL[r1 + k8 + lc + 4];
#pragma unroll
                for (int nt = 0; nt < 2; nt++) {
                    MMA_TF32(sacc[mt][nt], ah, bqh[nt][0], bqh[nt][1]);
                    MMA_TF32(sacc[mt][nt], ah, bql[nt][0], bql[nt][1]);
                    MMA_TF32(sacc[mt][nt], al, bqh[nt][0], bqh[nt][1]);
                }
            }
        }

        // ---- Causal mask on diagonal tile ----
        if (kt == qt) {
#pragma unroll
            for (int mt = 0; mt < 4; mt++)
#pragma unroll
                for (int nt = 0; nt < 2; nt++)
#pragma unroll
                    for (int c = 0; c < 4; c++) {
                        int kc = mt * 16 + lr + 8 * (c >> 1);
                        int qr = q0w + nt * 8 + 2 * lc + (c & 1);
                        if (kc > qr) sacc[mt][nt][c] = -1e30f;
                    }
        }

        // ---- Online softmax per q-row (rows live in S^T columns) ----
#pragma unroll
        for (int nt = 0; nt < 2; nt++) {
#pragma unroll
            for (int par = 0; par < 2; par++) {
                float rm = -1e30f;
#pragma unroll
                for (int mt = 0; mt < 4; mt++) {
                    rm = fmaxf(rm, sacc[mt][nt][par]);
                    rm = fmaxf(rm, sacc[mt][nt][2 + par]);
                }
                rm = fmaxf(rm, __shfl_xor_sync(0xffffffffu, rm, 4));
                rm = fmaxf(rm, __shfl_xor_sync(0xffffffffu, rm, 8));
                rm = fmaxf(rm, __shfl_xor_sync(0xffffffffu, rm, 16));
                float mnew = fmaxf(mrow[nt][par], rm);
                float corr = __expf(mrow[nt][par] - mnew);
                float rs = 0.f;
#pragma unroll
                for (int mt = 0; mt < 4; mt++) {
                    float p0 = __expf(sacc[mt][nt][par] - mnew);
                    float p1 = __expf(sacc[mt][nt][2 + par] - mnew);
                    sacc[mt][nt][par] = p0; sacc[mt][nt][2 + par] = p1;
                    rs += p0 + p1;
                }
                rs += __shfl_xor_sync(0xffffffffu, rs, 4);
                rs += __shfl_xor_sync(0xffffffffu, rs, 8);
                rs += __shfl_xor_sync(0xffffffffu, rs, 16);
                lrow[nt][par] = lrow[nt][par] * corr + rs;
                mrow[nt][par] = mnew;
                if (lr == 0) CORR[q0w + nt * 8 + 2 * lc + par] = corr;
            }
        }

        // ---- Store P^T (pairs of adjacent qrow cols) ----
#pragma unroll
        for (int mt = 0; mt < 4; mt++)
#pragma unroll
            for (int nt = 0; nt < 2; nt++)
#pragma unroll
                for (int h2 = 0; h2 < 2; h2++) {
                    int kc = mt * 16 + lr + 8 * h2;
                    int qq = q0w + nt * 8 + 2 * lc;
                    *(uint2*)&Pt[kc * SP_W + qq] = make_uint2(
                        f2tf32(sacc[mt][nt][2 * h2]),
                        f2tf32(sacc[mt][nt][2 * h2 + 1]));
                }
        __syncwarp();

        // ---- Rescale O, then O += P·V ----
        {
            float cA = CORR[q0w + lr], cB = CORR[q0w + lr + 8];
#pragma unroll
            for (int nt = 0; nt < 8; nt++) {
                oacc[nt][0] *= cA; oacc[nt][1] *= cA;
                oacc[nt][2] *= cB; oacc[nt][3] *= cB;
            }
        }
#pragma unroll
        for (int k8 = 0; k8 < 64; k8 += 8) {
            uint32_t a[4];
            a[0] = Pt[(k8 + lc) * SP_W + q0w + lr];
            a[1] = Pt[(k8 + lc) * SP_W + q0w + 8 + lr];
            a[2] = Pt[(k8 + lc + 4) * SP_W + q0w + lr];
            a[3] = Pt[(k8 + lc + 4) * SP_W + q0w + 8 + lr];
#pragma unroll
            for (int nt = 0; nt < 8; nt++) {
                uint32_t b0 = Vs[(k8 + lc) * SV_W + nt * 8 + lr];
                uint32_t b1 = Vs[(k8 + lc + 4) * SV_W + nt * 8 + lr];
                MMA_TF32(oacc[nt], a, b0, b1);
            }
        }
    }

    // ---- Epilogue: normalize and write concat layout ----
    if (lr == 0) {
#pragma unroll
        for (int nt = 0; nt < 2; nt++)
#pragma unroll
            for (int par = 0; par < 2; par++)
                LROW[q0w + nt * 8 + 2 * lc + par] = lrow[nt][par];
    }
    __syncwarp();
    {
        float iA = 1.0f / LROW[q0w + lr], iB = 1.0f / LROW[q0w + lr + 8];
        const int qA = qt * 64 + q0w + lr, qB = qA + 8;
        float* dA = g_c + (size_t)(b * SS + qA) * DD + h * 64;
        float* dB = g_c + (size_t)(b * SS + qB) * DD + h * 64;
#pragma unroll
        for (int nt = 0; nt < 8; nt++) {
            const int e = nt * 8 + 2 * lc;
            *(float2*)(dA + e) = make_float2(oacc[nt][0] * iA, oacc[nt][1] * iA);
            *(float2*)(dB + e) = make_float2(oacc[nt][2] * iB, oacc[nt][3] * iB);
        }
    }
}

// ---------------------------------------------------------------------------
// Kernel 3: output projection via tf32 mma.sync (byte-identical to R7/R8).
// ---------------------------------------------------------------------------
#define APAD 20
#define BPAD 136

__global__ __launch_bounds__(256) void oproj_mma(
    const float* __restrict__ Wo, float* __restrict__ Y)
{
    __shared__ uint32_t As[64 * APAD];
    __shared__ uint32_t Bs[16 * BPAD];

    const int tid = threadIdx.x;
    const int wid = tid >> 5, lane = tid & 31;
    const int m0w = (wid & 3) * 16, n0w = (wid >> 2) * 32;
    const int m0 = blockIdx.x * 64, n0 = blockIdx.y * 64;
    const int lr = lane >> 2, lc = lane & 3;

    float acc[4][4];
#pragma unroll
    for (int nt = 0; nt < 4; nt++)
#pragma unroll
        for (int i = 0; i < 4; i++) acc[nt][i] = 0.f;

    const int arow = tid >> 2, akseg = (tid & 3) * 4;

    for (int k0 = 0; k0 < DD; k0 += 16) {
        {
            float4 v = *(const float4*)&g_c[(size_t)(m0 + arow) * DD + k0 + akseg];
            uint32_t* d = &As[arow * APAD + akseg];
            d[0] = f2tf32(v.x); d[1] = f2tf32(v.y);
            d[2] = f2tf32(v.z); d[3] = f2tf32(v.w);
        }
        {
            float4 v = *(const float4*)&Wo[(size_t)(n0 + arow) * DD + k0 + akseg];
            Bs[(akseg + 0) * BPAD + arow] = f2tf32(v.x);
            Bs[(akseg + 1) * BPAD + arow] = f2tf32(v.y);
            Bs[(akseg + 2) * BPAD + arow] = f2tf32(v.z);
            Bs[(akseg + 3) * BPAD + arow] = f2tf32(v.w);
        }
        __syncthreads();

#pragma unroll
        for (int ks = 0; ks < 2; ks++) {
            const int k8 = ks * 8;
            uint32_t a[4];
            {
                const int r = (m0w + lr) * APAD;
                a[0] = As[r + k8 + lc];
                a[1] = As[r + 8 * APAD + k8 + lc];
                a[2] = As[r + k8 + lc + 4];
                a[3] = As[r + 8 * APAD + k8 + lc + 4];
            }
#pragma unroll
            for (int nt = 0; nt < 4; nt++) {
                const int n = n0w + nt * 8 + lr;
                uint32_t b0 = Bs[(k8 + lc) * BPAD + n];
                uint32_t b1 = Bs[(k8 + lc + 4) * BPAD + n];
                MMA_TF32(acc[nt], a, b0, b1);
            }
        }
        __syncthreads();
    }

#pragma unroll
    for (int half = 0; half < 2; half++) {
        const int m = m0 + m0w + lr + half * 8;
#pragma unroll
        for (int nt = 0; nt < 4; nt++) {
            const int e = n0w + nt * 8 + 2 * lc;
            *(float2*)&Y[(size_t)m * DD + n0 + e] =
                make_float2(acc[nt][half * 2], acc[nt][half * 2 + 1]);
        }
    }
}

// ---------------------------------------------------------------------------
extern "C" void kernel_launch(void* const* d_in, const int* in_sizes, int n_in,
                              void* d_out, int out_size)
{
    const float* x  = (const float*)d_in[0];
    const float* Wq = (const float*)d_in[1];
    const float* Wk = (const float*)d_in[2];
    const float* Wv = (const float*)d_in[3];
    const float* Wo = (const float*)d_in[4];
    float* y = (float*)d_out;

    const int attn_smem = ATTN_SMEM_WORDS * 4;  // 109056
    cudaFuncSetAttribute(attn_mma,
                         cudaFuncAttributeMaxDynamicSharedMemorySize, attn_smem);

    qkv_mma<<<dim3(MM/128, 48), 512>>>(x, Wq, Wk, Wv);
    attn_mma<<<dim3(SS/64, BB*HH), 128, attn_smem>>>();
    oproj_mma<<<dim3(MM/64, DD/64), 256>>>(Wo, y);
}

// round 11
// speedup vs baseline: 2.0881x; 1.1196x over previous
#include <cuda_runtime.h>
#include <cuda_bf16.h>
#include <cstdint>

#define BB 4
#define SS 2048
#define DD 1024
#define HH 16
#define HDD 64
#define MM (BB*SS)   // 8192

// Scratch (allocation-free rule: __device__ globals)
__device__ float g_q[(size_t)BB*HH*SS*HDD];   // [bh][s][e] 32MB
__device__ float g_k[(size_t)BB*HH*SS*HDD];
__device__ float g_v[(size_t)BB*HH*SS*HDD];
__device__ float g_c[(size_t)MM*DD];          // attn out, concat layout [b,s,D]

__device__ __forceinline__ uint32_t f2tf32(float f) {
    uint32_t u;
    asm("cvt.rna.tf32.f32 %0, %1;" : "=r"(u) : "f"(f));
    return u;
}

__device__ __forceinline__ void split_tf32(float x, uint32_t& hi, uint32_t& lo) {
    hi = f2tf32(x);
    lo = f2tf32(x - __uint_as_float(hi));
}

#define MMA_TF32(c, a, b0, b1) \
    asm volatile("mma.sync.aligned.m16n8k8.row.col.f32.tf32.tf32.f32 " \
        "{%0,%1,%2,%3}, {%4,%5,%6,%7}, {%8,%9}, {%0,%1,%2,%3};" \
        : "+f"((c)[0]), "+f"((c)[1]), "+f"((c)[2]), "+f"((c)[3]) \
        : "r"((a)[0]), "r"((a)[1]), "r"((a)[2]), "r"((a)[3]), "r"(b0), "r"(b1))

// ---------------------------------------------------------------------------
// Kernel 1: QKV projection via tf32 mma.sync.
// CTA 128x64 (one head per n-block), BK=32, 256 thr / 8 warps (4m x 2n),
// warp tile 32x32 -> 2 smem words per mma (was 3).
// ---------------------------------------------------------------------------
#define QAPAD 36
#define QBPAD 72

__global__ __launch_bounds__(256) void qkv_mma(
    const float* __restrict__ x,  const float* __restrict__ Wq,
    const float* __restrict__ Wk, const float* __restrict__ Wv)
{
    __shared__ uint32_t As[128 * QAPAD];   // [m][k] tf32 bits
    __shared__ uint32_t Bs[32 * QBPAD];    // [k][n] tf32 bits

    const int tid = threadIdx.x;
    const int wid = tid >> 5, lane = tid & 31;
    const int m0w = (wid & 3) * 32, n0w = (wid >> 2) * 32;
    const int m0 = blockIdx.x * 128;
    const int ct = blockIdx.y;                 // 0..47: which*16 + h
    const int which = ct >> 4, h = ct & 15;
    const float* W = (which == 0 ? Wq : which == 1 ? Wk : Wv)
                   + (size_t)h * DD * HDD;
    float* ob = (which == 0) ? g_q : (which == 1) ? g_k : g_v;

    const int lr = lane >> 2, lc = lane & 3;

    float acc[2][4][4];
#pragma unroll
    for (int mt = 0; mt < 2; mt++)
#pragma unroll
        for (int nt = 0; nt < 4; nt++)
#pragma unroll
            for (int i = 0; i < 4; i++) acc[mt][nt][i] = 0.f;

    for (int k0 = 0; k0 < DD; k0 += 32) {
        // ---- A tile: 128 x 32 f32 (4 float4/thread, coalesced) ----
#pragma unroll
        for (int i = 0; i < 4; i++) {
            int f4 = tid + i * 256;            // 1024 float4 = 128 rows x 8
            int row = f4 >> 3, c4 = f4 & 7;
            float4 v = *(const float4*)&x[(size_t)(m0 + row) * DD + k0 + c4 * 4];
            *(uint4*)&As[row * QAPAD + c4 * 4] =
                make_uint4(f2tf32(v.x), f2tf32(v.y), f2tf32(v.z), f2tf32(v.w));
        }
        // ---- B tile: 32 k-rows x 64 n (2 float4/thread, direct) ----
#pragma unroll
        for (int i = 0; i < 2; i++) {
            int f4 = tid + i * 256;            // 512 float4 = 32 rows x 16
            int row = f4 >> 4, c4 = f4 & 15;
            float4 v = *(const float4*)&W[(size_t)(k0 + row) * HDD + c4 * 4];
            *(uint4*)&Bs[row * QBPAD + c4 * 4] =
                make_uint4(f2tf32(v.x), f2tf32(v.y), f2tf32(v.z), f2tf32(v.w));
        }
        __syncthreads();

#pragma unroll
        for (int ks = 0; ks < 4; ks++) {
            const int k8 = ks * 8;
            uint32_t a[2][4];
#pragma unroll
            for (int mt = 0; mt < 2; mt++) {
                const int r = (m0w + mt * 16 + lr) * QAPAD;
                a[mt][0] = As[r + k8 + lc];
                a[mt][1] = As[r + 8 * QAPAD + k8 + lc];
                a[mt][2] = As[r + k8 + lc + 4];
                a[mt][3] = As[r + 8 * QAPAD + k8 + lc + 4];
            }
#pragma unroll
            for (int nt = 0; nt < 4; nt++) {
                const int n = n0w + nt * 8 + lr;
                uint32_t b0 = Bs[(k8 + lc) * QBPAD + n];
                uint32_t b1 = Bs[(k8 + lc + 4) * QBPAD + n];
                MMA_TF32(acc[0][nt], a[0], b0, b1);
                MMA_TF32(acc[1][nt], a[1], b0, b1);
            }
        }
        __syncthreads();
    }

    // ---- Epilogue: scatter into [bh][s][e] ----
#pragma unroll
    for (int mt = 0; mt < 2; mt++)
#pragma unroll
    for (int half = 0; half < 2; half++) {
        const int m = m0 + m0w + mt * 16 + lr + half * 8;
        const int b = m >> 11, srow = m & (SS - 1);
        float* dst = ob + ((size_t)(b * HH + h) * SS + srow) * HDD;
#pragma unroll
        for (int nt = 0; nt < 4; nt++) {
            const int e = n0w + nt * 8 + 2 * lc;
            *(float2*)(dst + e) =
                make_float2(acc[mt][nt][half * 2], acc[mt][nt][half * 2 + 1]);
        }
    }
}

// ---------------------------------------------------------------------------
// Kernel 2: flash attention via tf32 mma.sync (byte-identical to R9 pass).
// ---------------------------------------------------------------------------
#define SQ_W 72
#define SK_W 68
#define SV_W 72
#define SP_W 72

#define OFF_QTH 0
#define OFF_QTL 4608
#define OFF_KAH 9216
#define OFF_KAL 13568
#define OFF_VS  17920
#define OFF_PT  22528
#define OFF_CORR 27136
#define OFF_LROW 27200
#define ATTN_SMEM_WORDS 27264   // * 4 = 109056 bytes

__global__ __launch_bounds__(128) void attn_mma() {
    extern __shared__ uint32_t smw[];
    uint32_t* QtH = smw + OFF_QTH;
    uint32_t* QtL = smw + OFF_QTL;
    uint32_t* KaH = smw + OFF_KAH;
    uint32_t* KaL = smw + OFF_KAL;
    uint32_t* Vs  = smw + OFF_VS;
    uint32_t* Pt  = smw + OFF_PT;
    float* CORR = (float*)(smw + OFF_CORR);
    float* LROW = (float*)(smw + OFF_LROW);

    const int qt = blockIdx.x, bh = blockIdx.y;
    const int b = bh >> 4, h = bh & 15;
    const float* qb = g_q + (size_t)bh * SS * HDD + (size_t)qt * 64 * HDD;
    const float* kb = g_k + (size_t)bh * SS * HDD;
    const float* vb = g_v + (size_t)bh * SS * HDD;

    const int tid = threadIdx.x, wr = tid >> 5, lane = tid & 31;
    const int lr = lane >> 2, lc = lane & 3;
    const int q0w = wr * 16;

#pragma unroll
    for (int i = 0; i < 8; i++) {
        int f4 = tid + i * 128;
        int row = f4 >> 4, c4 = f4 & 15;
        float4 v = *(const float4*)&qb[(size_t)row * HDD + c4 * 4];
        float xv[4] = {v.x, v.y, v.z, v.w};
#pragma unroll
        for (int j = 0; j < 4; j++) {
            uint32_t hi, lo;
            split_tf32(xv[j] * 0.125f, hi, lo);
            QtH[(c4 * 4 + j) * SQ_W + row] = hi;
            QtL[(c4 * 4 + j) * SQ_W + row] = lo;
        }
    }

    float oacc[8][4];
#pragma unroll
    for (int nt = 0; nt < 8; nt++)
#pragma unroll
        for (int i = 0; i < 4; i++) oacc[nt][i] = 0.f;
    float mrow[2][2] = {{-1e30f, -1e30f}, {-1e30f, -1e30f}};
    float lrow[2][2] = {{0.f, 0.f}, {0.f, 0.f}};

    for (int kt = 0; kt <= qt; kt++) {
        __syncthreads();
#pragma unroll
        for (int i = 0; i < 8; i++) {
            int f4 = tid + i * 128;
            int row = f4 >> 4, c4 = f4 & 15;
            float4 kv = *(const float4*)&kb[(size_t)(kt * 64 + row) * HDD + c4 * 4];
            uint4 h4, l4;
            split_tf32(kv.x, h4.x, l4.x); split_tf32(kv.y, h4.y, l4.y);
            split_tf32(kv.z, h4.z, l4.z); split_tf32(kv.w, h4.w, l4.w);
            *(uint4*)&KaH[row * SK_W + c4 * 4] = h4;
            *(uint4*)&KaL[row * SK_W + c4 * 4] = l4;
            float4 vv = *(const float4*)&vb[(size_t)(kt * 64 + row) * HDD + c4 * 4];
            *(uint4*)&Vs[row * SV_W + c4 * 4] =
                make_uint4(f2tf32(vv.x), f2tf32(vv.y), f2tf32(vv.z), f2tf32(vv.w));
        }
        __syncthreads();

        float sacc[4][2][4];
#pragma unroll
        for (int mt = 0; mt < 4; mt++)
#pragma unroll
            for (int nt = 0; nt < 2; nt++)
#pragma unroll
                for (int i = 0; i < 4; i++) sacc[mt][nt][i] = 0.f;

#pragma unroll
        for (int k8 = 0; k8 < 64; k8 += 8) {
            uint32_t bqh[2][2], bql[2][2];
#pragma unroll
            for (int nt = 0; nt < 2; nt++) {
                const int nq = q0w + nt * 8 + lr;
                bqh[nt][0] = QtH[(k8 + lc) * SQ_W + nq];
                bqh[nt][1] = QtH[(k8 + lc + 4) * SQ_W + nq];
                bql[nt][0] = QtL[(k8 + lc) * SQ_W + nq];
                bql[nt][1] = QtL[(k8 + lc + 4) * SQ_W + nq];
            }
#pragma unroll
            for (int mt = 0; mt < 4; mt++) {
                uint32_t ah[4], al[4];
                const int r0 = (mt * 16 + lr) * SK_W, r1 = (mt * 16 + 8 + lr) * SK_W;
                ah[0] = KaH[r0 + k8 + lc];     ah[1] = KaH[r1 + k8 + lc];
                ah[2] = KaH[r0 + k8 + lc + 4]; ah[3] = KaH[r1 + k8 + lc + 4];
                al[0] = KaL[r0 + k8 + lc];     al[1] = KaL[r1 + k8 + lc];
                al[2] = KaL[r0 + k8 + lc + 4]; al[3] = KaL[r1 + k8 + lc + 4];
#pragma unroll
                for (int nt = 0; nt < 2; nt++) {
                    MMA_TF32(sacc[mt][nt], ah, bqh[nt][0], bqh[nt][1]);
                    MMA_TF32(sacc[mt][nt], ah, bql[nt][0], bql[nt][1]);
                    MMA_TF32(sacc[mt][nt], al, bqh[nt][0], bqh[nt][1]);
                }
            }
        }

        if (kt == qt) {
#pragma unroll
            for (int mt = 0; mt < 4; mt++)
#pragma unroll
                for (int nt = 0; nt < 2; nt++)
#pragma unroll
                    for (int c = 0; c < 4; c++) {
                        int kc = mt * 16 + lr + 8 * (c >> 1);
                        int qr = q0w + nt * 8 + 2 * lc + (c & 1);
                        if (kc > qr) sacc[mt][nt][c] = -1e30f;
                    }
        }

#pragma unroll
        for (int nt = 0; nt < 2; nt++) {
#pragma unroll
            for (int par = 0; par < 2; par++) {
                float rm = -1e30f;
#pragma unroll
                for (int mt = 0; mt < 4; mt++) {
                    rm = fmaxf(rm, sacc[mt][nt][par]);
                    rm = fmaxf(rm, sacc[mt][nt][2 + par]);
                }
                rm = fmaxf(rm, __shfl_xor_sync(0xffffffffu, rm, 4));
                rm = fmaxf(rm, __shfl_xor_sync(0xffffffffu, rm, 8));
                rm = fmaxf(rm, __shfl_xor_sync(0xffffffffu, rm, 16));
                float mnew = fmaxf(mrow[nt][par], rm);
                float corr = __expf(mrow[nt][par] - mnew);
                float rs = 0.f;
#pragma unroll
                for (int mt = 0; mt < 4; mt++) {
                    float p0 = __expf(sacc[mt][nt][par] - mnew);
                    float p1 = __expf(sacc[mt][nt][2 + par] - mnew);
                    sacc[mt][nt][par] = p0; sacc[mt][nt][2 + par] = p1;
                    rs += p0 + p1;
                }
                rs += __shfl_xor_sync(0xffffffffu, rs, 4);
                rs += __shfl_xor_sync(0xffffffffu, rs, 8);
                rs += __shfl_xor_sync(0xffffffffu, rs, 16);
                lrow[nt][par] = lrow[nt][par] * corr + rs;
                mrow[nt][par] = mnew;
                if (lr == 0) CORR[q0w + nt * 8 + 2 * lc + par] = corr;
            }
        }

#pragma unroll
        for (int mt = 0; mt < 4; mt++)
#pragma unroll
            for (int nt = 0; nt < 2; nt++)
#pragma unroll
                for (int h2 = 0; h2 < 2; h2++) {
                    int kc = mt * 16 + lr + 8 * h2;
                    int qq = q0w + nt * 8 + 2 * lc;
                    *(uint2*)&Pt[kc * SP_W + qq] = make_uint2(
                        f2tf32(sacc[mt][nt][2 * h2]),
                        f2tf32(sacc[mt][nt][2 * h2 + 1]));
                }
        __syncwarp();

        {
            float cA = CORR[q0w + lr], cB = CORR[q0w + lr + 8];
#pragma unroll
            for (int nt = 0; nt < 8; nt++) {
                oacc[nt][0] *= cA; oacc[nt][1] *= cA;
                oacc[nt][2] *= cB; oacc[nt][3] *= cB;
            }
        }
#pragma unroll
        for (int k8 = 0; k8 < 64; k8 += 8) {
            uint32_t a[4];
            a[0] = Pt[(k8 + lc) * SP_W + q0w + lr];
            a[1] = Pt[(k8 + lc) * SP_W + q0w + 8 + lr];
            a[2] = Pt[(k8 + lc + 4) * SP_W + q0w + lr];
            a[3] = Pt[(k8 + lc + 4) * SP_W + q0w + 8 + lr];
#pragma unroll
            for (int nt = 0; nt < 8; nt++) {
                uint32_t b0 = Vs[(k8 + lc) * SV_W + nt * 8 + lr];
                uint32_t b1 = Vs[(k8 + lc + 4) * SV_W + nt * 8 + lr];
                MMA_TF32(oacc[nt], a, b0, b1);
            }
        }
    }

    if (lr == 0) {
#pragma unroll
        for (int nt = 0; nt < 2; nt++)
#pragma unroll
            for (int par = 0; par < 2; par++)
                LROW[q0w + nt * 8 + 2 * lc + par] = lrow[nt][par];
    }
    __syncwarp();
    {
        float iA = 1.0f / LROW[q0w + lr], iB = 1.0f / LROW[q0w + lr + 8];
        const int qA = qt * 64 + q0w + lr, qB = qA + 8;
        float* dA = g_c + (size_t)(b * SS + qA) * DD + h * 64;
        float* dB = g_c + (size_t)(b * SS + qB) * DD + h * 64;
#pragma unroll
        for (int nt = 0; nt < 8; nt++) {
            const int e = nt * 8 + 2 * lc;
            *(float2*)(dA + e) = make_float2(oacc[nt][0] * iA, oacc[nt][1] * iA);
            *(float2*)(dB + e) = make_float2(oacc[nt][2] * iB, oacc[nt][3] * iB);
        }
    }
}

// ---------------------------------------------------------------------------
// Kernel 3: output projection via tf32 mma.sync.
// CTA 128x64, BK=16, 256 thr / 8 warps (4m x 2n), warp tile 32x32.
// Loaders keep R7's proven mappings (B transpose-gather unchanged).
// ---------------------------------------------------------------------------
#define APAD 20
#define BPAD 136

__global__ __launch_bounds__(256) void oproj_mma(
    const float* __restrict__ Wo, float* __restrict__ Y)
{
    __shared__ uint32_t As[128 * APAD];   // [m][k] tf32 bits
    __shared__ uint32_t Bs[16 * BPAD];    // [k][n] tf32 bits

    const int tid = threadIdx.x;
    const int wid = tid >> 5, lane = tid & 31;
    const int m0w = (wid & 3) * 32, n0w = (wid >> 2) * 32;
    const int m0 = blockIdx.x * 128, n0 = blockIdx.y * 64;
    const int lr = lane >> 2, lc = lane & 3;

    float acc[2][4][4];
#pragma unroll
    for (int mt = 0; mt < 2; mt++)
#pragma unroll
        for (int nt = 0; nt < 4; nt++)
#pragma unroll
            for (int i = 0; i < 4; i++) acc[mt][nt][i] = 0.f;

    const int brow = tid >> 2, bkseg = (tid & 3) * 4;   // B loader (R7 mapping)

    for (int k0 = 0; k0 < DD; k0 += 16) {
        // A tile: 128 x 16 f32 from g_c (2 float4/thread, coalesced)
#pragma unroll
        for (int i = 0; i < 2; i++) {
            int f4 = tid + i * 256;            // 512 float4 = 128 rows x 4
            int row = f4 >> 2, c4 = f4 & 3;
            float4 v = *(const float4*)&g_c[(size_t)(m0 + row) * DD + k0 + c4 * 4];
            *(uint4*)&As[row * APAD + c4 * 4] =
                make_uint4(f2tf32(v.x), f2tf32(v.y), f2tf32(v.z), f2tf32(v.w));
        }
        // B tile: Wo rows are output cols -> k-major Bs[k][n] (R7 gather)
        {
            float4 v = *(const float4*)&Wo[(size_t)(n0 + brow) * DD + k0 + bkseg];
            Bs[(bkseg + 0) * BPAD + brow] = f2tf32(v.x);
            Bs[(bkseg + 1) * BPAD + brow] = f2tf32(v.y);
            Bs[(bkseg + 2) * BPAD + brow] = f2tf32(v.z);
            Bs[(bkseg + 3) * BPAD + brow] = f2tf32(v.w);
        }
        __syncthreads();

#pragma unroll
        for (int ks = 0; ks < 2; ks++) {
            const int k8 = ks * 8;
            uint32_t a[2][4];
#pragma unroll
            for (int mt = 0; mt < 2; mt++) {
                const int r = (m0w + mt * 16 + lr) * APAD;
                a[mt][0] = As[r + k8 + lc];
                a[mt][1] = As[r + 8 * APAD + k8 + lc];
                a[mt][2] = As[r + k8 + lc + 4];
                a[mt][3] = As[r + 8 * APAD + k8 + lc + 4];
            }
#pragma unroll
            for (int nt = 0; nt < 4; nt++) {
                const int n = n0w + nt * 8 + lr;
                uint32_t b0 = Bs[(k8 + lc) * BPAD + n];
                uint32_t b1 = Bs[(k8 + lc + 4) * BPAD + n];
                MMA_TF32(acc[0][nt], a[0], b0, b1);
                MMA_TF32(acc[1][nt], a[1], b0, b1);
            }
        }
        __syncthreads();
    }

#pragma unroll
    for (int mt = 0; mt < 2; mt++)
#pragma unroll
    for (int half = 0; half < 2; half++) {
        const int m = m0 + m0w + mt * 16 + lr + half * 8;
#pragma unroll
        for (int nt = 0; nt < 4; nt++) {
            const int e = n0w + nt * 8 + 2 * lc;
            *(float2*)&Y[(size_t)m * DD + n0 + e] =
                make_float2(acc[mt][nt][half * 2], acc[mt][nt][half * 2 + 1]);
        }
    }
}

// ---------------------------------------------------------------------------
extern "C" void kernel_launch(void* const* d_in, const int* in_sizes, int n_in,
                              void* d_out, int out_size)
{
    const float* x  = (const float*)d_in[0];
    const float* Wq = (const float*)d_in[1];
    const float* Wk = (const float*)d_in[2];
    const float* Wv = (const float*)d_in[3];
    const float* Wo = (const float*)d_in[4];
    float* y = (float*)d_out;

    const int attn_smem = ATTN_SMEM_WORDS * 4;  // 109056
    cudaFuncSetAttribute(attn_mma,
                         cudaFuncAttributeMaxDynamicSharedMemorySize, attn_smem);

    qkv_mma<<<dim3(MM/128, 48), 256>>>(x, Wq, Wk, Wv);
    attn_mma<<<dim3(SS/64, BB*HH), 128, attn_smem>>>();
    oproj_mma<<<dim3(MM/128, DD/64), 256>>>(Wo, y);
}

// round 12
// speedup vs baseline: 2.1352x; 1.0225x over previous
#include <cuda_runtime.h>
#include <cuda_bf16.h>
#include <cstdint>

#define BB 4
#define SS 2048
#define DD 1024
#define HH 16
#define HDD 64
#define MM (BB*SS)   // 8192

// Scratch (allocation-free rule: __device__ globals)
__device__ float g_q[(size_t)BB*HH*SS*HDD];   // [bh][s][e] 32MB
__device__ float g_k[(size_t)BB*HH*SS*HDD];
__device__ float g_v[(size_t)BB*HH*SS*HDD];
__device__ float g_c[(size_t)MM*DD];          // attn out, concat layout [b,s,D]

__device__ __forceinline__ uint32_t f2tf32(float f) {
    uint32_t u;
    asm("cvt.rna.tf32.f32 %0, %1;" : "=r"(u) : "f"(f));
    return u;
}

__device__ __forceinline__ void split_tf32(float x, uint32_t& hi, uint32_t& lo) {
    hi = f2tf32(x);
    lo = f2tf32(x - __uint_as_float(hi));
}

#define MMA_TF32(c, a, b0, b1) \
    asm volatile("mma.sync.aligned.m16n8k8.row.col.f32.tf32.tf32.f32 " \
        "{%0,%1,%2,%3}, {%4,%5,%6,%7}, {%8,%9}, {%0,%1,%2,%3};" \
        : "+f"((c)[0]), "+f"((c)[1]), "+f"((c)[2]), "+f"((c)[3]) \
        : "r"((a)[0]), "r"((a)[1]), "r"((a)[2]), "r"((a)[3]), "r"(b0), "r"(b1))

// ---------------------------------------------------------------------------
// Kernel 1: QKV projection via tf32 mma.sync.
// CTA 256x64 (one head per n-block), BK=32, 256 thr / 8 warps (4m x 2n),
// warp tile 64x32 -> 1.5 smem words per mma (was 2.0).
// ---------------------------------------------------------------------------
#define QAPAD 36
#define QBPAD 72

__global__ __launch_bounds__(256) void qkv_mma(
    const float* __restrict__ x,  const float* __restrict__ Wq,
    const float* __restrict__ Wk, const float* __restrict__ Wv)
{
    __shared__ uint32_t As[256 * QAPAD];   // [m][k] tf32 bits
    __shared__ uint32_t Bs[32 * QBPAD];    // [k][n] tf32 bits

    const int tid = threadIdx.x;
    const int wid = tid >> 5, lane = tid & 31;
    const int m0w = (wid & 3) * 64, n0w = (wid >> 2) * 32;
    const int m0 = blockIdx.x * 256;
    const int ct = blockIdx.y;                 // 0..47: which*16 + h
    const int which = ct >> 4, h = ct & 15;
    const float* W = (which == 0 ? Wq : which == 1 ? Wk : Wv)
                   + (size_t)h * DD * HDD;
    float* ob = (which == 0) ? g_q : (which == 1) ? g_k : g_v;

    const int lr = lane >> 2, lc = lane & 3;

    float acc[4][4][4];
#pragma unroll
    for (int mt = 0; mt < 4; mt++)
#pragma unroll
        for (int nt = 0; nt < 4; nt++)
#pragma unroll
            for (int i = 0; i < 4; i++) acc[mt][nt][i] = 0.f;

    for (int k0 = 0; k0 < DD; k0 += 32) {
        // ---- A tile: 256 x 32 f32 (8 float4/thread, coalesced) ----
#pragma unroll
        for (int i = 0; i < 8; i++) {
            int f4 = tid + i * 256;            // 2048 float4 = 256 rows x 8
            int row = f4 >> 3, c4 = f4 & 7;
            float4 v = *(const float4*)&x[(size_t)(m0 + row) * DD + k0 + c4 * 4];
            *(uint4*)&As[row * QAPAD + c4 * 4] =
                make_uint4(f2tf32(v.x), f2tf32(v.y), f2tf32(v.z), f2tf32(v.w));
        }
        // ---- B tile: 32 k-rows x 64 n (2 float4/thread, direct) ----
#pragma unroll
        for (int i = 0; i < 2; i++) {
            int f4 = tid + i * 256;            // 512 float4 = 32 rows x 16
            int row = f4 >> 4, c4 = f4 & 15;
            float4 v = *(const float4*)&W[(size_t)(k0 + row) * HDD + c4 * 4];
            *(uint4*)&Bs[row * QBPAD + c4 * 4] =
                make_uint4(f2tf32(v.x), f2tf32(v.y), f2tf32(v.z), f2tf32(v.w));
        }
        __syncthreads();

#pragma unroll
        for (int ks = 0; ks < 4; ks++) {
            const int k8 = ks * 8;
            uint32_t a[4][4];
#pragma unroll
            for (int mt = 0; mt < 4; mt++) {
                const int r = (m0w + mt * 16 + lr) * QAPAD;
                a[mt][0] = As[r + k8 + lc];
                a[mt][1] = As[r + 8 * QAPAD + k8 + lc];
                a[mt][2] = As[r + k8 + lc + 4];
                a[mt][3] = As[r + 8 * QAPAD + k8 + lc + 4];
            }
#pragma unroll
            for (int nt = 0; nt < 4; nt++) {
                const int n = n0w + nt * 8 + lr;
                uint32_t b0 = Bs[(k8 + lc) * QBPAD + n];
                uint32_t b1 = Bs[(k8 + lc + 4) * QBPAD + n];
#pragma unroll
                for (int mt = 0; mt < 4; mt++)
                    MMA_TF32(acc[mt][nt], a[mt], b0, b1);
            }
        }
        __syncthreads();
    }

    // ---- Epilogue: scatter into [bh][s][e] ----
#pragma unroll
    for (int mt = 0; mt < 4; mt++)
#pragma unroll
    for (int half = 0; half < 2; half++) {
        const int m = m0 + m0w + mt * 16 + lr + half * 8;
        const int b = m >> 11, srow = m & (SS - 1);
        float* dst = ob + ((size_t)(b * HH + h) * SS + srow) * HDD;
#pragma unroll
        for (int nt = 0; nt < 4; nt++) {
            const int e = n0w + nt * 8 + 2 * lc;
            *(float2*)(dst + e) =
                make_float2(acc[mt][nt][half * 2], acc[mt][nt][half * 2 + 1]);
        }
    }
}

// ---------------------------------------------------------------------------
// Kernel 2: flash attention via tf32 mma.sync (byte-identical to R9/R10).
// ---------------------------------------------------------------------------
#define SQ_W 72
#define SK_W 68
#define SV_W 72
#define SP_W 72

#define OFF_QTH 0
#define OFF_QTL 4608
#define OFF_KAH 9216
#define OFF_KAL 13568
#define OFF_VS  17920
#define OFF_PT  22528
#define OFF_CORR 27136
#define OFF_LROW 27200
#define ATTN_SMEM_WORDS 27264   // * 4 = 109056 bytes

__global__ __launch_bounds__(128) void attn_mma() {
    extern __shared__ uint32_t smw[];
    uint32_t* QtH = smw + OFF_QTH;
    uint32_t* QtL = smw + OFF_QTL;
    uint32_t* KaH = smw + OFF_KAH;
    uint32_t* KaL = smw + OFF_KAL;
    uint32_t* Vs  = smw + OFF_VS;
    uint32_t* Pt  = smw + OFF_PT;
    float* CORR = (float*)(smw + OFF_CORR);
    float* LROW = (float*)(smw + OFF_LROW);

    const int qt = blockIdx.x, bh = blockIdx.y;
    const int b = bh >> 4, h = bh & 15;
    const float* qb = g_q + (size_t)bh * SS * HDD + (size_t)qt * 64 * HDD;
    const float* kb = g_k + (size_t)bh * SS * HDD;
    const float* vb = g_v + (size_t)bh * SS * HDD;

    const int tid = threadIdx.x, wr = tid >> 5, lane = tid & 31;
    const int lr = lane >> 2, lc = lane & 3;
    const int q0w = wr * 16;

#pragma unroll
    for (int i = 0; i < 8; i++) {
        int f4 = tid + i * 128;
        int row = f4 >> 4, c4 = f4 & 15;
        float4 v = *(const float4*)&qb[(size_t)row * HDD + c4 * 4];
        float xv[4] = {v.x, v.y, v.z, v.w};
#pragma unroll
        for (int j = 0; j < 4; j++) {
            uint32_t hi, lo;
            split_tf32(xv[j] * 0.125f, hi, lo);
            QtH[(c4 * 4 + j) * SQ_W + row] = hi;
            QtL[(c4 * 4 + j) * SQ_W + row] = lo;
        }
    }

    float oacc[8][4];
#pragma unroll
    for (int nt = 0; nt < 8; nt++)
#pragma unroll
        for (int i = 0; i < 4; i++) oacc[nt][i] = 0.f;
    float mrow[2][2] = {{-1e30f, -1e30f}, {-1e30f, -1e30f}};
    float lrow[2][2] = {{0.f, 0.f}, {0.f, 0.f}};

    for (int kt = 0; kt <= qt; kt++) {
        __syncthreads();
#pragma unroll
        for (int i = 0; i < 8; i++) {
            int f4 = tid + i * 128;
            int row = f4 >> 4, c4 = f4 & 15;
            float4 kv = *(const float4*)&kb[(size_t)(kt * 64 + row) * HDD + c4 * 4];
            uint4 h4, l4;
            split_tf32(kv.x, h4.x, l4.x); split_tf32(kv.y, h4.y, l4.y);
            split_tf32(kv.z, h4.z, l4.z); split_tf32(kv.w, h4.w, l4.w);
            *(uint4*)&KaH[row * SK_W + c4 * 4] = h4;
            *(uint4*)&KaL[row * SK_W + c4 * 4] = l4;
            float4 vv = *(const float4*)&vb[(size_t)(kt * 64 + row) * HDD + c4 * 4];
            *(uint4*)&Vs[row * SV_W + c4 * 4] =
                make_uint4(f2tf32(vv.x), f2tf32(vv.y), f2tf32(vv.z), f2tf32(vv.w));
        }
        __syncthreads();

        float sacc[4][2][4];
#pragma unroll
        for (int mt = 0; mt < 4; mt++)
#pragma unroll
            for (int nt = 0; nt < 2; nt++)
#pragma unroll
                for (int i = 0; i < 4; i++) sacc[mt][nt][i] = 0.f;

#pragma unroll
        for (int k8 = 0; k8 < 64; k8 += 8) {
            uint32_t bqh[2][2], bql[2][2];
#pragma unroll
            for (int nt = 0; nt < 2; nt++) {
                const int nq = q0w + nt * 8 + lr;
                bqh[nt][0] = QtH[(k8 + lc) * SQ_W + nq];
                bqh[nt][1] = QtH[(k8 + lc + 4) * SQ_W + nq];
                bql[nt][0] = QtL[(k8 + lc) * SQ_W + nq];
                bql[nt][1] = QtL[(k8 + lc + 4) * SQ_W + nq];
            }
#pragma unroll
            for (int mt = 0; mt < 4; mt++) {
                uint32_t ah[4], al[4];
                const int r0 = (mt * 16 + lr) * SK_W, r1 = (mt * 16 + 8 + lr) * SK_W;
                ah[0] = KaH[r0 + k8 + lc];     ah[1] = KaH[r1 + k8 + lc];
                ah[2] = KaH[r0 + k8 + lc + 4]; ah[3] = KaH[r1 + k8 + lc + 4];
                al[0] = KaL[r0 + k8 + lc];     al[1] = KaL[r1 + k8 + lc];
                al[2] = KaL[r0 + k8 + lc + 4]; al[3] = KaL[r1 + k8 + lc + 4];
#pragma unroll
                for (int nt = 0; nt < 2; nt++) {
                    MMA_TF32(sacc[mt][nt], ah, bqh[nt][0], bqh[nt][1]);
                    MMA_TF32(sacc[mt][nt], ah, bql[nt][0], bql[nt][1]);
                    MMA_TF32(sacc[mt][nt], al, bqh[nt][0], bqh[nt][1]);
                }
            }
        }

        if (kt == qt) {
#pragma unroll
            for (int mt = 0; mt < 4; mt++)
#pragma unroll
                for (int nt = 0; nt < 2; nt++)
#pragma unroll
                    for (int c = 0; c < 4; c++) {
                        int kc = mt * 16 + lr + 8 * (c >> 1);
                        int qr = q0w + nt * 8 + 2 * lc + (c & 1);
                        if (kc > qr) sacc[mt][nt][c] = -1e30f;
                    }
        }

#pragma unroll
        for (int nt = 0; nt < 2; nt++) {
#pragma unroll
            for (int par = 0; par < 2; par++) {
                float rm = -1e30f;
#pragma unroll
                for (int mt = 0; mt < 4; mt++) {
                    rm = fmaxf(rm, sacc[mt][nt][par]);
                    rm = fmaxf(rm, sacc[mt][nt][2 + par]);
                }
                rm = fmaxf(rm, __shfl_xor_sync(0xffffffffu, rm, 4));
                rm = fmaxf(rm, __shfl_xor_sync(0xffffffffu, rm, 8));
                rm = fmaxf(rm, __shfl_xor_sync(0xffffffffu, rm, 16));
                float mnew = fmaxf(mrow[nt][par], rm);
                float corr = __expf(mrow[nt][par] - mnew);
                float rs = 0.f;
#pragma unroll
                for (int mt = 0; mt < 4; mt++) {
                    float p0 = __expf(sacc[mt][nt][par] - mnew);
                    float p1 = __expf(sacc[mt][nt][2 + par] - mnew);
                    sacc[mt][nt][par] = p0; sacc[mt][nt][2 + par] = p1;
                    rs += p0 + p1;
                }
                rs += __shfl_xor_sync(0xffffffffu, rs, 4);
                rs += __shfl_xor_sync(0xffffffffu, rs, 8);
                rs += __shfl_xor_sync(0xffffffffu, rs, 16);
                lrow[nt][par] = lrow[nt][par] * corr + rs;
                mrow[nt][par] = mnew;
                if (lr == 0) CORR[q0w + nt * 8 + 2 * lc + par] = corr;
            }
        }

#pragma unroll
        for (int mt = 0; mt < 4; mt++)
#pragma unroll
            for (int nt = 0; nt < 2; nt++)
#pragma unroll
                for (int h2 = 0; h2 < 2; h2++) {
                    int kc = mt * 16 + lr + 8 * h2;
                    int qq = q0w + nt * 8 + 2 * lc;
                    *(uint2*)&Pt[kc * SP_W + qq] = make_uint2(
                        f2tf32(sacc[mt][nt][2 * h2]),
                        f2tf32(sacc[mt][nt][2 * h2 + 1]));
                }
        __syncwarp();

        {
            float cA = CORR[q0w + lr], cB = CORR[q0w + lr + 8];
#pragma unroll
            for (int nt = 0; nt < 8; nt++) {
                oacc[nt][0] *= cA; oacc[nt][1] *= cA;
                oacc[nt][2] *= cB; oacc[nt][3] *= cB;
            }
        }
#pragma unroll
        for (int k8 = 0; k8 < 64; k8 += 8) {
            uint32_t a[4];
            a[0] = Pt[(k8 + lc) * SP_W + q0w + lr];
            a[1] = Pt[(k8 + lc) * SP_W + q0w + 8 + lr];
            a[2] = Pt[(k8 + lc + 4) * SP_W + q0w + lr];
            a[3] = Pt[(k8 + lc + 4) * SP_W + q0w + 8 + lr];
#pragma unroll
            for (int nt = 0; nt < 8; nt++) {
                uint32_t b0 = Vs[(k8 + lc) * SV_W + nt * 8 + lr];
                uint32_t b1 = Vs[(k8 + lc + 4) * SV_W + nt * 8 + lr];
                MMA_TF32(oacc[nt], a, b0, b1);
            }
        }
    }

    if (lr == 0) {
#pragma unroll
        for (int nt = 0; nt < 2; nt++)
#pragma unroll
            for (int par = 0; par < 2; par++)
                LROW[q0w + nt * 8 + 2 * lc + par] = lrow[nt][par];
    }
    __syncwarp();
    {
        float iA = 1.0f / LROW[q0w + lr], iB = 1.0f / LROW[q0w + lr + 8];
        const int qA = qt * 64 + q0w + lr, qB = qA + 8;
        float* dA = g_c + (size_t)(b * SS + qA) * DD + h * 64;
        float* dB = g_c + (size_t)(b * SS + qB) * DD + h * 64;
#pragma unroll
        for (int nt = 0; nt < 8; nt++) {
            const int e = nt * 8 + 2 * lc;
            *(float2*)(dA + e) = make_float2(oacc[nt][0] * iA, oacc[nt][1] * iA);
            *(float2*)(dB + e) = make_float2(oacc[nt][2] * iB, oacc[nt][3] * iB);
        }
    }
}

// ---------------------------------------------------------------------------
// Kernel 3: output projection via tf32 mma.sync.
// CTA 256x64, BK=16, 256 thr / 8 warps (4m x 2n), warp tile 64x32.
// ---------------------------------------------------------------------------
#define APAD 20
#define BPAD 136

__global__ __launch_bounds__(256) void oproj_mma(
    const float* __restrict__ Wo, float* __restrict__ Y)
{
    __shared__ uint32_t As[256 * APAD];   // [m][k] tf32 bits
    __shared__ uint32_t Bs[16 * BPAD];    // [k][n] tf32 bits

    const int tid = threadIdx.x;
    const int wid = tid >> 5, lane = tid & 31;
    const int m0w = (wid & 3) * 64, n0w = (wid >> 2) * 32;
    const int m0 = blockIdx.x * 256, n0 = blockIdx.y * 64;
    const int lr = lane >> 2, lc = lane & 3;

    float acc[4][4][4];
#pragma unroll
    for (int mt = 0; mt < 4; mt++)
#pragma unroll
        for (int nt = 0; nt < 4; nt++)
#pragma unroll
            for (int i = 0; i < 4; i++) acc[mt][nt][i] = 0.f;

    const int brow = tid >> 2, bkseg = (tid & 3) * 4;   // B loader (R7 mapping)

    for (int k0 = 0; k0 < DD; k0 += 16) {
        // A tile: 256 x 16 f32 from g_c (4 float4/thread, coalesced)
#pragma unroll
        for (int i = 0; i < 4; i++) {
            int f4 = tid + i * 256;            // 1024 float4 = 256 rows x 4
            int row = f4 >> 2, c4 = f4 & 3;
            float4 v = *(const float4*)&g_c[(size_t)(m0 + row) * DD + k0 + c4 * 4];
            *(uint4*)&As[row * APAD + c4 * 4] =
                make_uint4(f2tf32(v.x), f2tf32(v.y), f2tf32(v.z), f2tf32(v.w));
        }
        // B tile: Wo rows are output cols -> k-major Bs[k][n] (R7 gather)
        {
            float4 v = *(const float4*)&Wo[(size_t)(n0 + brow) * DD + k0 + bkseg];
            Bs[(bkseg + 0) * BPAD + brow] = f2tf32(v.x);
            Bs[(bkseg + 1) * BPAD + brow] = f2tf32(v.y);
            Bs[(bkseg + 2) * BPAD + brow] = f2tf32(v.z);
            Bs[(bkseg + 3) * BPAD + brow] = f2tf32(v.w);
        }
        __syncthreads();

#pragma unroll
        for (int ks = 0; ks < 2; ks++) {
            const int k8 = ks * 8;
            uint32_t a[4][4];
#pragma unroll
            for (int mt = 0; mt < 4; mt++) {
                const int r = (m0w + mt * 16 + lr) * APAD;
                a[mt][0] = As[r + k8 + lc];
                a[mt][1] = As[r + 8 * APAD + k8 + lc];
                a[mt][2] = As[r + k8 + lc + 4];
                a[mt][3] = As[r + 8 * APAD + k8 + lc + 4];
            }
#pragma unroll
            for (int nt = 0; nt < 4; nt++) {
                const int n = n0w + nt * 8 + lr;
                uint32_t b0 = Bs[(k8 + lc) * BPAD + n];
                uint32_t b1 = Bs[(k8 + lc + 4) * BPAD + n];
#pragma unroll
                for (int mt = 0; mt < 4; mt++)
                    MMA_TF32(acc[mt][nt], a[mt], b0, b1);
            }
        }
        __syncthreads();
    }

#pragma unroll
    for (int mt = 0; mt < 4; mt++)
#pragma unroll
    for (int half = 0; half < 2; half++) {
        const int m = m0 + m0w + mt * 16 + lr + half * 8;
#pragma unroll
        for (int nt = 0; nt < 4; nt++) {
            const int e = n0w + nt * 8 + 2 * lc;
            *(float2*)&Y[(size_t)m * DD + n0 + e] =
                make_float2(acc[mt][nt][half * 2], acc[mt][nt][half * 2 + 1]);
        }
    }
}

// ---------------------------------------------------------------------------
extern "C" void kernel_launch(void* const* d_in, const int* in_sizes, int n_in,
                              void* d_out, int out_size)
{
    const float* x  = (const float*)d_in[0];
    const float* Wq = (const float*)d_in[1];
    const float* Wk = (const float*)d_in[2];
    const float* Wv = (const float*)d_in[3];
    const float* Wo = (const float*)d_in[4];
    float* y = (float*)d_out;

    const int attn_smem = ATTN_SMEM_WORDS * 4;  // 109056
    cudaFuncSetAttribute(attn_mma,
                         cudaFuncAttributeMaxDynamicSharedMemorySize, attn_smem);

    qkv_mma<<<dim3(MM/256, 48), 256>>>(x, Wq, Wk, Wv);
    attn_mma<<<dim3(SS/64, BB*HH), 128, attn_smem>>>();
    oproj_mma<<<dim3(MM/256, DD/64), 256>>>(Wo, y);
}